// round 6
// baseline (speedup 1.0000x reference)
#include <cuda_runtime.h>
#include <cuda_bf16.h>

#define BB   8
#define SS   2048
#define KIN  512
#define NIN  2048
#define NP   4096
#define HID  4096
#define DM   1024
#define KSEL 256
#define NC   512

typedef unsigned long long ull;
typedef unsigned int u32;

// ---------------- scratch ----------------
__device__ __align__(256) __nv_bfloat16 g_Asp[(size_t)BB * 2 * SS * KIN];
__device__ __align__(256) __nv_bfloat16 g_Bh [(size_t)BB * NP * KIN];
__device__ __align__(256) __nv_bfloat16 g_Bc [(size_t)BB * 2 * NC * KIN];
__device__ __align__(256) __nv_bfloat16 g_PC [(size_t)BB * 2 * SS * NC];
__device__ __align__(256) __nv_bfloat16 g_PA [(size_t)BB * 2 * SS * KSEL];
__device__ __align__(256) __nv_bfloat16 g_Pr [(size_t)BB * 2 * DM * KSEL];
__device__ float    g_mask[BB * NIN];
__device__ float    g_h[BB * HID];
__device__ float    g_sig[BB * NP];
__device__ unsigned g_scoreEnc[BB * NP];
__device__ unsigned g_scoreEnc2[BB * NC];
__device__ int      g_pidx512[BB * NC];
__device__ int      g_pidx[BB * KSEL];
__device__ int      g_cmap[BB * KSEL];

// ---------------- helpers ----------------
__device__ __forceinline__ unsigned fenc(float f) {
    unsigned u = __float_as_uint(f);
    return (u & 0x80000000u) ? ~u : (u | 0x80000000u);
}
__device__ __forceinline__ float fdec(unsigned u) {
    return __uint_as_float((u & 0x80000000u) ? (u & 0x7fffffffu) : ~u);
}
__device__ __forceinline__ float gelu_f(float x) {
    return 0.5f * x * (1.0f + erff(x * 0.70710678118654752f));
}
__device__ __forceinline__ u32 smem_u32(const void* p) {
    u32 a; asm("{ .reg .u64 t; cvta.to.shared.u64 t, %1; cvt.u32.u64 %0, t; }" : "=r"(a) : "l"(p));
    return a;
}
__device__ __forceinline__ void split2(float a, __nv_bfloat16& h, __nv_bfloat16& m) {
    h = __float2bfloat16(a);
    m = __float2bfloat16(a - __bfloat162float(h));
}

// ---------------- mma.sync / ldmatrix / cp.async ----------------
__device__ __forceinline__ void mma16816(float* d, const u32* a, u32 b0, u32 b1) {
    asm volatile("mma.sync.aligned.m16n8k16.row.col.f32.bf16.bf16.f32 "
        "{%0,%1,%2,%3}, {%4,%5,%6,%7}, {%8,%9}, {%0,%1,%2,%3};"
        : "+f"(d[0]), "+f"(d[1]), "+f"(d[2]), "+f"(d[3])
        : "r"(a[0]), "r"(a[1]), "r"(a[2]), "r"(a[3]), "r"(b0), "r"(b1));
}
__device__ __forceinline__ void ldsm4(u32* r, u32 addr) {
    asm volatile("ldmatrix.sync.aligned.m8n8.x4.shared.b16 {%0,%1,%2,%3}, [%4];"
        : "=r"(r[0]), "=r"(r[1]), "=r"(r[2]), "=r"(r[3]) : "r"(addr));
}
__device__ __forceinline__ void cpasync16(u32 dst, const void* src) {
    asm volatile("cp.async.cg.shared.global [%0], [%1], 16;" :: "r"(dst), "l"(src));
}
#define CP_COMMIT() asm volatile("cp.async.commit_group;" ::: "memory")
#define CP_WAIT(n)  asm volatile("cp.async.wait_group %0;" :: "n"(n) : "memory")

#define RPAD   80
#define PLANE  (128 * RPAD)          // 10240
#define BPLANE (256 * RPAD)          // 20480
#define SUB1   (PLANE + BPLANE)      // gemm1a sub-slab: 30720
#define GSMEM1 (4 * SUB1)            // 2 stages x 2 subs = 122880
#define SUB4   (4 * PLANE)           // refine/gemm3t sub-slab: 40960
#define GSMEM4 (4 * SUB4)            // 2 stages x 2 subs = 163840

// ---------------- init kernels ----------------
__global__ void k_initMask() {
    int t = blockIdx.x * blockDim.x + threadIdx.x;
    if (t < BB * NIN) g_mask[t] = 0.0f;
}
__global__ void k_initScore() {
    int t = blockIdx.x * blockDim.x + threadIdx.x;
    if (t < BB * NP)  g_scoreEnc[t] = 0u;
    if (t < BB * NC)  g_scoreEnc2[t] = 0u;
}
__global__ void k_scatter(const int* __restrict__ sidx) {
    int t = blockIdx.x * blockDim.x + threadIdx.x;
    if (t < BB * KIN) {
        int b = t >> 9;
        g_mask[b * NIN + sidx[t]] = 1.0f;
    }
}

// ---------------- split A planes ----------------
union B4U { __nv_bfloat16 h[4]; ull u; };
union B2U { __nv_bfloat16 h[2]; u32 u; };

__global__ void k_splitAh(const float* __restrict__ act) {
    size_t t = (size_t)blockIdx.x * 256 + threadIdx.x;
    size_t bs = t >> 7;
    int k4 = (int)(t & 127);
    int b = (int)(bs >> 11), s = (int)(bs & 2047);
    float4 v = ((const float4*)act)[t];
    float vv[4] = { v.x, v.y, v.z, v.w };
    B4U hh;
#pragma unroll
    for (int i = 0; i < 4; i++) hh.h[i] = __float2bfloat16(vv[i]);
    *(ull*)(g_Asp + ((size_t)(b * 2) * SS + s) * KIN + k4 * 4) = hh.u;
}

__global__ void k_splitAm(const float* __restrict__ act) {
    size_t t = (size_t)blockIdx.x * 256 + threadIdx.x;
    size_t bs = t >> 7;
    int k4 = (int)(t & 127);
    int b = (int)(bs >> 11), s = (int)(bs & 2047);
    float4 v = ((const float4*)act)[t];
    float vv[4] = { v.x, v.y, v.z, v.w };
    B4U mm;
#pragma unroll
    for (int i = 0; i < 4; i++) {
        __nv_bfloat16 h = __float2bfloat16(vv[i]);
        mm.h[i] = __float2bfloat16(vv[i] - __bfloat162float(h));
    }
    *(ull*)(g_Asp + ((size_t)(b * 2 + 1) * SS + s) * KIN + k4 * 4) = mm.u;
}

// ---------------- gather B h-plane (full 4096 rows) ----------------
__global__ void k_gatherBh(const float* __restrict__ cw, const int* __restrict__ sidx) {
    __shared__ float row[NIN];
    __shared__ int sidxS[BB * KIN];    // 16 KB
    int p = blockIdx.x, tid = threadIdx.x;
    for (int i = tid; i < NIN; i += 256) row[i] = cw[(size_t)p * NIN + i];
    for (int i = tid; i < BB * KIN / 4; i += 256)
        ((int4*)sidxS)[i] = ((const int4*)sidx)[i];
    __syncthreads();
    int k = tid * 2;
#pragma unroll 1
    for (int b = 0; b < BB; b++) {
        int i0 = sidxS[b * KIN + k], i1 = sidxS[b * KIN + k + 1];
        B2U hh;
        hh.h[0] = __float2bfloat16(row[i0]);
        hh.h[1] = __float2bfloat16(row[i1]);
        *(u32*)(g_Bh + ((size_t)b * NP + p) * KIN + k) = hh.u;
    }
}

// ---------------- gather B splits for 512 candidates ----------------
__global__ void k_gatherB512(const float* __restrict__ cw, const int* __restrict__ sidx) {
    __shared__ float row[NIN];
    int blk = blockIdx.x;
    int b = blk >> 9, j = blk & (NC - 1);
    int tid = threadIdx.x;
    int p = g_pidx512[b * NC + j];
    for (int i = tid; i < NIN; i += 256) row[i] = cw[(size_t)p * NIN + i];
    __syncthreads();
    int k = tid * 2;
    int i0 = sidx[b * KIN + k], i1 = sidx[b * KIN + k + 1];
    B2U hh, mm;
    split2(row[i0], hh.h[0], mm.h[0]);
    split2(row[i1], hh.h[1], mm.h[1]);
    const size_t PL = (size_t)NC * KIN;
    size_t base = ((size_t)(b * 2) * NC + j) * KIN + k;
    *(u32*)(g_Bc + base)      = hh.u;
    *(u32*)(g_Bc + base + PL) = mm.u;
}

// ---------------- K1a: approx score GEMM, 128x256 tile, k-slab 64 ----------------
__global__ __launch_bounds__(256)
void k_gemm1a() {
    extern __shared__ char smem[];
    const u32 sbase = smem_u32(smem);
    const int tid = threadIdx.x;
    const int wid = tid >> 5, lid = tid & 31;
    const int wm = wid & 3, wn = wid >> 2;
    const int b  = blockIdx.z;
    const int p0 = blockIdx.x * 256;
    const int s0 = blockIdx.y * 128;

    float acc[2][16][4];
#pragma unroll
    for (int i = 0; i < 2; i++)
#pragma unroll
        for (int j = 0; j < 16; j++)
#pragma unroll
            for (int r = 0; r < 4; r++) acc[i][j][r] = 0.0f;

    auto load_stage = [&](int ks, int buf) {
        const int k0 = ks * 64;
#pragma unroll
        for (int sub = 0; sub < 2; sub++) {
            const int kk0 = k0 + sub * 32;
            u32 sgA = sbase + buf * (2 * SUB1) + sub * SUB1;
            u32 sgB = sgA + PLANE;
#pragma unroll
            for (int i = 0; i < 2; i++) {
                int idx = tid + i * 256;
                int r = idx >> 2, c = idx & 3;
                const __nv_bfloat16* g = g_Asp + ((size_t)(b * 2) * SS + s0 + r) * KIN + kk0 + c * 8;
                cpasync16(sgA + r * RPAD + c * 16, g);
            }
#pragma unroll
            for (int i = 0; i < 4; i++) {
                int idx = tid + i * 256;
                int r = idx >> 2, c = idx & 3;
                const __nv_bfloat16* g = g_Bh + ((size_t)b * NP + p0 + r) * KIN + kk0 + c * 8;
                cpasync16(sgB + r * RPAD + c * 16, g);
            }
        }
    };

    const u32 aoff = (u32)((wm * 32 + (lid & 15)) * RPAD + (lid >> 4) * 16);
    const u32 boff = (u32)((wn * 128 + (lid & 15)) * RPAD + (lid >> 4) * 16);

    load_stage(0, 0); CP_COMMIT();

#pragma unroll 1
    for (int ks = 0; ks < KIN / 64; ks++) {
        int buf = ks & 1;
        if (ks < KIN / 64 - 1) { load_stage(ks + 1, buf ^ 1); CP_COMMIT(); CP_WAIT(1); }
        else                   { CP_WAIT(0); }
        __syncthreads();
#pragma unroll
        for (int sub = 0; sub < 2; sub++) {
            u32 sA = sbase + buf * (2 * SUB1) + sub * SUB1;
            u32 sB = sA + PLANE;
#pragma unroll
            for (int kk = 0; kk < 2; kk++) {
                u32 ah[2][4];
#pragma unroll
                for (int mt = 0; mt < 2; mt++)
                    ldsm4(ah[mt], sA + aoff + mt * (16 * RPAD) + kk * 32);
                u32 bh[8][4];
#pragma unroll
                for (int q = 0; q < 8; q++)
                    ldsm4(bh[q], sB + boff + q * (16 * RPAD) + kk * 32);
#pragma unroll
                for (int mt = 0; mt < 2; mt++)
#pragma unroll
                    for (int q = 0; q < 8; q++) {
                        mma16816(acc[mt][2 * q],     ah[mt], bh[q][0], bh[q][2]);
                        mma16816(acc[mt][2 * q + 1], ah[mt], bh[q][1], bh[q][3]);
                    }
            }
        }
        __syncthreads();
    }

    u32* scol = (u32*)smem;
    if (tid < 256) scol[tid] = 0u;
    __syncthreads();
#pragma unroll
    for (int nt = 0; nt < 16; nt++) {
        float m0 = fmaxf(fmaxf(acc[0][nt][0], acc[0][nt][2]), fmaxf(acc[1][nt][0], acc[1][nt][2]));
        float m1 = fmaxf(fmaxf(acc[0][nt][1], acc[0][nt][3]), fmaxf(acc[1][nt][1], acc[1][nt][3]));
#pragma unroll
        for (int mk = 4; mk < 32; mk <<= 1) {
            m0 = fmaxf(m0, __shfl_xor_sync(0xffffffffu, m0, mk));
            m1 = fmaxf(m1, __shfl_xor_sync(0xffffffffu, m1, mk));
        }
        if (lid < 4) {
            atomicMax(&scol[wn * 128 + nt * 8 + 2 * lid],     fenc(m0));
            atomicMax(&scol[wn * 128 + nt * 8 + 2 * lid + 1], fenc(m1));
        }
    }
    __syncthreads();
    if (tid < 256) atomicMax(&g_scoreEnc[b * NP + p0 + tid], scol[tid]);
}

// ---------------- K2: hidden MLP ----------------
__global__ void k_hidden(const float* __restrict__ w1, const float* __restrict__ b1) {
    int j = blockIdx.x;
    int tid = threadIdx.x;
    const float* wr = w1 + (size_t)j * NIN;
    float acc[BB];
#pragma unroll
    for (int b = 0; b < BB; b++) acc[b] = 0.0f;
    for (int n = tid; n < NIN; n += 256) {
        float w = wr[n];
#pragma unroll
        for (int b = 0; b < BB; b++) acc[b] += w * g_mask[b * NIN + n];
    }
    __shared__ float red[BB][256];
#pragma unroll
    for (int b = 0; b < BB; b++) red[b][tid] = acc[b];
    __syncthreads();
    for (int s1 = 128; s1 > 0; s1 >>= 1) {
        if (tid < s1) {
#pragma unroll
            for (int b = 0; b < BB; b++) red[b][tid] += red[b][tid + s1];
        }
        __syncthreads();
    }
    if (tid < BB) g_h[tid * HID + j] = gelu_f(red[tid][0] + b1[j]);
}

// ---------------- K3a: relevance -> sigmoid (float4) ----------------
__global__ void k_relsig(const float* __restrict__ w2, const float* __restrict__ b2) {
    int warp = threadIdx.x >> 5, lane = threadIdx.x & 31;
    int p = blockIdx.x * 8 + warp;
    const float4* wr = (const float4*)(w2 + (size_t)p * HID);
    float acc[BB];
#pragma unroll
    for (int b = 0; b < BB; b++) acc[b] = 0.0f;
#pragma unroll 4
    for (int j = lane; j < HID / 4; j += 32) {
        float4 w = wr[j];
#pragma unroll
        for (int b = 0; b < BB; b++) {
            float4 h = ((const float4*)(g_h + b * HID))[j];
            acc[b] += w.x * h.x + w.y * h.y + w.z * h.z + w.w * h.w;
        }
    }
#pragma unroll
    for (int o = 16; o > 0; o >>= 1)
#pragma unroll
        for (int b = 0; b < BB; b++) acc[b] += __shfl_down_sync(0xffffffffu, acc[b], o);
    if (lane == 0) {
#pragma unroll
        for (int b = 0; b < BB; b++) {
            float rel = acc[b] + b2[p];
            g_sig[b * NP + p] = 1.0f / (1.0f + expf(-rel));
        }
    }
}

// ---------------- K4: approx top-512 (score computed inline) ----------------
__global__ void k_topk512() {
    __shared__ ull key[NP];
    int b = blockIdx.x, tid = threadIdx.x;
    for (int i = tid; i < NP; i += 1024) {
        float sc = gelu_f(fdec(g_scoreEnc[b * NP + i])) * g_sig[b * NP + i];
        key[i] = ((ull)fenc(sc) << 32) | (unsigned)i;
    }
    __syncthreads();
    for (int k = 2; k <= NP; k <<= 1) {
        for (int j = k >> 1; j > 0; j >>= 1) {
            for (int i = tid; i < NP; i += 1024) {
                int ix = i ^ j;
                if (ix > i) {
                    ull x = key[i], y = key[ix];
                    bool desc = ((i & k) == 0);
                    if (desc ? (x < y) : (x > y)) { key[i] = y; key[ix] = x; }
                }
            }
            __syncthreads();
        }
    }
    if (tid < NC) g_pidx512[b * NC + tid] = (int)(key[tid] & 0xffffffffu);
}

// ---------------- K5: refine — exact 3-pass z for 512 cands, k-slab 64 ----------------
__global__ __launch_bounds__(256)
void k_refine() {
    extern __shared__ char smem[];
    const u32 sbase = smem_u32(smem);
    const int tid = threadIdx.x;
    const int wid = tid >> 5, lid = tid & 31;
    const int wm = wid & 3, wn = wid >> 2;
    const int b  = blockIdx.z;
    const int n0 = blockIdx.x * 128;
    const int s0 = blockIdx.y * 128;

    float acc[2][8][4];
#pragma unroll
    for (int i = 0; i < 2; i++)
#pragma unroll
        for (int j = 0; j < 8; j++)
#pragma unroll
            for (int r = 0; r < 4; r++) acc[i][j][r] = 0.0f;

    auto load_stage = [&](int ks, int buf) {
        const int k0 = ks * 64;
#pragma unroll
        for (int sub = 0; sub < 2; sub++) {
            const int kk0 = k0 + sub * 32;
            u32 sg = sbase + buf * (2 * SUB4) + sub * SUB4;
#pragma unroll
            for (int i = 0; i < 4; i++) {
                int idx = tid + i * 256;
                int sp = idx >> 9, rem = idx & 511;
                int r = rem >> 2, c = rem & 3;
                const __nv_bfloat16* g = g_Asp + ((size_t)(b * 2 + sp) * SS + s0 + r) * KIN + kk0 + c * 8;
                cpasync16(sg + sp * PLANE + r * RPAD + c * 16, g);
            }
#pragma unroll
            for (int i = 0; i < 4; i++) {
                int idx = tid + i * 256;
                int sp = idx >> 9, rem = idx & 511;
                int r = rem >> 2, c = rem & 3;
                const __nv_bfloat16* g = g_Bc + ((size_t)(b * 2 + sp) * NC + n0 + r) * KIN + kk0 + c * 8;
                cpasync16(sg + 2 * PLANE + sp * PLANE + r * RPAD + c * 16, g);
            }
        }
    };

    const u32 aoff = (u32)((wm * 32 + (lid & 15)) * RPAD + (lid >> 4) * 16);
    const u32 boff = (u32)((wn * 64 + (lid & 15)) * RPAD + (lid >> 4) * 16);

    load_stage(0, 0); CP_COMMIT();

#pragma unroll 1
    for (int ks = 0; ks < KIN / 64; ks++) {
        int buf = ks & 1;
        if (ks < KIN / 64 - 1) { load_stage(ks + 1, buf ^ 1); CP_COMMIT(); CP_WAIT(1); }
        else                   { CP_WAIT(0); }
        __syncthreads();
#pragma unroll
        for (int sub = 0; sub < 2; sub++) {
            u32 sA = sbase + buf * (2 * SUB4) + sub * SUB4;
            u32 sB = sA + 2 * PLANE;
#pragma unroll
            for (int kk = 0; kk < 2; kk++) {
                u32 ah[2][4], am[2][4];
#pragma unroll
                for (int mt = 0; mt < 2; mt++) {
                    ldsm4(ah[mt], sA + aoff + mt * (16 * RPAD) + kk * 32);
                    ldsm4(am[mt], sA + PLANE + aoff + mt * (16 * RPAD) + kk * 32);
                }
                u32 bh[4][4], bm[4][4];
#pragma unroll
                for (int nt2 = 0; nt2 < 4; nt2++) {
                    ldsm4(bh[nt2], sB + boff + nt2 * (16 * RPAD) + kk * 32);
                    ldsm4(bm[nt2], sB + PLANE + boff + nt2 * (16 * RPAD) + kk * 32);
                }
#pragma unroll
                for (int mt = 0; mt < 2; mt++)
#pragma unroll
                    for (int nt2 = 0; nt2 < 4; nt2++) {
                        mma16816(acc[mt][2 * nt2],     ah[mt], bh[nt2][0], bh[nt2][2]);
                        mma16816(acc[mt][2 * nt2 + 1], ah[mt], bh[nt2][1], bh[nt2][3]);
                        mma16816(acc[mt][2 * nt2],     ah[mt], bm[nt2][0], bm[nt2][2]);
                        mma16816(acc[mt][2 * nt2 + 1], ah[mt], bm[nt2][1], bm[nt2][3]);
                        mma16816(acc[mt][2 * nt2],     am[mt], bh[nt2][0], bh[nt2][2]);
                        mma16816(acc[mt][2 * nt2 + 1], am[mt], bh[nt2][1], bh[nt2][3]);
                    }
            }
        }
        __syncthreads();
    }

    u32* scol = (u32*)smem;
    if (tid < 128) scol[tid] = 0u;
    __syncthreads();

    const size_t PL = (size_t)SS * NC;
#pragma unroll
    for (int mt = 0; mt < 2; mt++)
#pragma unroll
        for (int nt = 0; nt < 8; nt++) {
            int row = s0 + wm * 32 + mt * 16 + (lid >> 2);
            int col = n0 + wn * 64 + nt * 8 + 2 * (lid & 3);
            float g0 = gelu_f(acc[mt][nt][0]), g1 = gelu_f(acc[mt][nt][1]);
            float g2 = gelu_f(acc[mt][nt][2]), g3 = gelu_f(acc[mt][nt][3]);
            B2U h01, m01, h23, m23;
            split2(g0, h01.h[0], m01.h[0]); split2(g1, h01.h[1], m01.h[1]);
            split2(g2, h23.h[0], m23.h[0]); split2(g3, h23.h[1], m23.h[1]);
            size_t base = ((size_t)(b * 2) * SS + row) * NC + col;
            *(u32*)(g_PC + base)               = h01.u;
            *(u32*)(g_PC + base + PL)          = m01.u;
            *(u32*)(g_PC + base + 8 * NC)      = h23.u;
            *(u32*)(g_PC + base + PL + 8 * NC) = m23.u;
        }
#pragma unroll
    for (int nt = 0; nt < 8; nt++) {
        float m0 = fmaxf(fmaxf(acc[0][nt][0], acc[0][nt][2]), fmaxf(acc[1][nt][0], acc[1][nt][2]));
        float m1 = fmaxf(fmaxf(acc[0][nt][1], acc[0][nt][3]), fmaxf(acc[1][nt][1], acc[1][nt][3]));
#pragma unroll
        for (int mk = 4; mk < 32; mk <<= 1) {
            m0 = fmaxf(m0, __shfl_xor_sync(0xffffffffu, m0, mk));
            m1 = fmaxf(m1, __shfl_xor_sync(0xffffffffu, m1, mk));
        }
        if (lid < 4) {
            atomicMax(&scol[wn * 64 + nt * 8 + 2 * lid],     fenc(m0));
            atomicMax(&scol[wn * 64 + nt * 8 + 2 * lid + 1], fenc(m1));
        }
    }
    __syncthreads();
    if (tid < 128) atomicMax(&g_scoreEnc2[b * NC + n0 + tid], scol[tid]);
}

// ---------------- K6: exact rescore + top-256 ----------------
__global__ void k_rescore() {
    __shared__ ull key[NC];
    int b = blockIdx.x, tid = threadIdx.x;   // 512 threads
    if (tid < NC) {
        float z = fdec(g_scoreEnc2[b * NC + tid]);
        int p = g_pidx512[b * NC + tid];
        float sc = gelu_f(z) * g_sig[b * NP + p];
        key[tid] = ((ull)fenc(sc) << 32) | (unsigned)tid;
    }
    __syncthreads();
    for (int k = 2; k <= NC; k <<= 1) {
        for (int j = k >> 1; j > 0; j >>= 1) {
            int i = tid;
            int ix = i ^ j;
            if (ix > i && i < NC) {
                ull x = key[i], y = key[ix];
                bool desc = ((i & k) == 0);
                if (desc ? (x < y) : (x > y)) { key[i] = y; key[ix] = x; }
            }
            __syncthreads();
        }
    }
    if (tid < KSEL) {
        int slot = (int)(key[tid] & 0xffffffffu);
        g_cmap[b * KSEL + tid] = slot;
        g_pidx[b * KSEL + tid] = g_pidx512[b * NC + slot];
    }
}

// ---------------- K7: compact via smem staging (coalesced) ----------------
__global__ void k_compact() {
    __shared__ __nv_bfloat16 st[2][8][NC];   // 16 KB
    __shared__ int cm[KSEL];
    int blk = blockIdx.x;                    // BB * SS/8 blocks
    int b = blk / (SS / 8);
    int s8 = (blk % (SS / 8)) * 8;
    int tid = threadIdx.x;
    if (tid < KSEL) cm[tid] = g_cmap[b * KSEL + tid];
    const int4* src0 = (const int4*)(g_PC + ((size_t)(b * 2)     * SS + s8) * NC);
    const int4* src1 = (const int4*)(g_PC + ((size_t)(b * 2 + 1) * SS + s8) * NC);
    int4* d0 = (int4*)&st[0][0][0];
    int4* d1 = (int4*)&st[1][0][0];
#pragma unroll
    for (int i = 0; i < 2; i++) {            // 8 rows * 512 bf16 = 512 int4 per plane
        int idx = tid + i * 256;
        d0[idx] = src0[idx];
        d1[idx] = src1[idx];
    }
    __syncthreads();
    int j = tid;
    int c = cm[j];
    const size_t PLa = (size_t)SS * KSEL;
#pragma unroll
    for (int r = 0; r < 8; r++) {
        size_t dst = ((size_t)(b * 2) * SS + s8 + r) * KSEL + j;
        g_PA[dst]       = st[0][r][c];
        g_PA[dst + PLa] = st[1][r][c];
    }
}

// ---------------- K8: gather + transpose + split proj rows ----------------
__global__ void k_projsplit(const float* __restrict__ proj) {
    __shared__ float t[32][33];
    __shared__ int pj[32];
    int j0 = blockIdx.x * 32, d0 = blockIdx.y * 32, b = blockIdx.z;
    int tx = threadIdx.x, ty = threadIdx.y;
    if (ty == 0) pj[tx] = g_pidx[b * KSEL + j0 + tx];
    __syncthreads();
#pragma unroll
    for (int i = 0; i < 32; i += 8) {
        int p = pj[ty + i];
        t[ty + i][tx] = proj[(size_t)p * DM + d0 + tx];
    }
    __syncthreads();
    const size_t PL = (size_t)DM * KSEL;
#pragma unroll
    for (int i = 0; i < 32; i += 8) {
        float v = t[tx][ty + i];
        __nv_bfloat16 h, m;
        split2(v, h, m);
        size_t base = ((size_t)(b * 2) * DM + d0 + ty + i) * KSEL + j0 + tx;
        g_Pr[base]      = h;
        g_Pr[base + PL] = m;
    }
}

// ---------------- K9: final GEMM (HMMA 3-pass), k-slab 64 ----------------
__global__ __launch_bounds__(256)
void k_gemm3t(float* __restrict__ out) {
    extern __shared__ char smem[];
    const u32 sbase = smem_u32(smem);
    const int tid = threadIdx.x;
    const int wid = tid >> 5, lid = tid & 31;
    const int wm = wid & 3, wn = wid >> 2;
    const int b  = blockIdx.z;
    const int d0 = blockIdx.x * 128;
    const int s0 = blockIdx.y * 128;

    float acc[2][8][4];
#pragma unroll
    for (int i = 0; i < 2; i++)
#pragma unroll
        for (int j = 0; j < 8; j++)
#pragma unroll
            for (int r = 0; r < 4; r++) acc[i][j][r] = 0.0f;

    auto load_stage = [&](int ks, int buf) {
        const int k0 = ks * 64;
#pragma unroll
        for (int sub = 0; sub < 2; sub++) {
            const int kk0 = k0 + sub * 32;
            u32 sg = sbase + buf * (2 * SUB4) + sub * SUB4;
#pragma unroll
            for (int i = 0; i < 4; i++) {
                int idx = tid + i * 256;
                int sp = idx >> 9, rem = idx & 511;
                int r = rem >> 2, c = rem & 3;
                const __nv_bfloat16* g = g_PA + ((size_t)(b * 2 + sp) * SS + s0 + r) * KSEL + kk0 + c * 8;
                cpasync16(sg + sp * PLANE + r * RPAD + c * 16, g);
            }
#pragma unroll
            for (int i = 0; i < 4; i++) {
                int idx = tid + i * 256;
                int sp = idx >> 9, rem = idx & 511;
                int r = rem >> 2, c = rem & 3;
                const __nv_bfloat16* g = g_Pr + ((size_t)(b * 2 + sp) * DM + d0 + r) * KSEL + kk0 + c * 8;
                cpasync16(sg + 2 * PLANE + sp * PLANE + r * RPAD + c * 16, g);
            }
        }
    };

    const u32 aoff = (u32)((wm * 32 + (lid & 15)) * RPAD + (lid >> 4) * 16);
    const u32 boff = (u32)((wn * 64 + (lid & 15)) * RPAD + (lid >> 4) * 16);

    load_stage(0, 0); CP_COMMIT();

#pragma unroll 1
    for (int ks = 0; ks < KSEL / 64; ks++) {
        int buf = ks & 1;
        if (ks < KSEL / 64 - 1) { load_stage(ks + 1, buf ^ 1); CP_COMMIT(); CP_WAIT(1); }
        else                    { CP_WAIT(0); }
        __syncthreads();
#pragma unroll
        for (int sub = 0; sub < 2; sub++) {
            u32 sA = sbase + buf * (2 * SUB4) + sub * SUB4;
            u32 sB = sA + 2 * PLANE;
#pragma unroll
            for (int kk = 0; kk < 2; kk++) {
                u32 ah[2][4], am[2][4];
#pragma unroll
                for (int mt = 0; mt < 2; mt++) {
                    ldsm4(ah[mt], sA + aoff + mt * (16 * RPAD) + kk * 32);
                    ldsm4(am[mt], sA + PLANE + aoff + mt * (16 * RPAD) + kk * 32);
                }
                u32 bh[4][4], bm[4][4];
#pragma unroll
                for (int nt2 = 0; nt2 < 4; nt2++) {
                    ldsm4(bh[nt2], sB + boff + nt2 * (16 * RPAD) + kk * 32);
                    ldsm4(bm[nt2], sB + PLANE + boff + nt2 * (16 * RPAD) + kk * 32);
                }
#pragma unroll
                for (int mt = 0; mt < 2; mt++)
#pragma unroll
                    for (int nt2 = 0; nt2 < 4; nt2++) {
                        mma16816(acc[mt][2 * nt2],     ah[mt], bh[nt2][0], bh[nt2][2]);
                        mma16816(acc[mt][2 * nt2 + 1], ah[mt], bh[nt2][1], bh[nt2][3]);
                        mma16816(acc[mt][2 * nt2],     ah[mt], bm[nt2][0], bm[nt2][2]);
                        mma16816(acc[mt][2 * nt2 + 1], ah[mt], bm[nt2][1], bm[nt2][3]);
                        mma16816(acc[mt][2 * nt2],     am[mt], bh[nt2][0], bh[nt2][2]);
                        mma16816(acc[mt][2 * nt2 + 1], am[mt], bh[nt2][1], bh[nt2][3]);
                    }
            }
        }
        __syncthreads();
    }
#pragma unroll
    for (int mt = 0; mt < 2; mt++)
#pragma unroll
        for (int nt = 0; nt < 8; nt++) {
            int row = s0 + wm * 32 + mt * 16 + (lid >> 2);
            int col = d0 + wn * 64 + nt * 8 + 2 * (lid & 3);
            float* po = out + ((size_t)b * SS + row) * DM + col;
            *(float2*)po            = make_float2(acc[mt][nt][0], acc[mt][nt][1]);
            *(float2*)(po + 8 * DM) = make_float2(acc[mt][nt][2], acc[mt][nt][3]);
        }
}

// ---------------- entry (multi-stream fork/join) ----------------
extern "C" void kernel_launch(void* const* d_in, const int* in_sizes, int n_in,
                              void* d_out, int out_size) {
    const float* act  = (const float*)d_in[0];
    const int*   sidx = (const int*)d_in[1];
    int o = (n_in >= 9 && in_sizes[2] == 1) ? 3 : 2;
    const float* cw   = (const float*)d_in[o + 0];
    const float* proj = (const float*)d_in[o + 1];
    const float* w1   = (const float*)d_in[o + 2];
    const float* b1   = (const float*)d_in[o + 3];
    const float* w2   = (const float*)d_in[o + 4];
    const float* b2   = (const float*)d_in[o + 5];
    float* out = (float*)d_out;

    static cudaStream_t s1 = nullptr;
    static cudaEvent_t ev0 = nullptr, ev1 = nullptr, ev2 = nullptr, ev3 = nullptr;
    if (s1 == nullptr) {
        cudaStreamCreateWithFlags(&s1, cudaStreamNonBlocking);
        cudaEventCreateWithFlags(&ev0, cudaEventDisableTiming);
        cudaEventCreateWithFlags(&ev1, cudaEventDisableTiming);
        cudaEventCreateWithFlags(&ev2, cudaEventDisableTiming);
        cudaEventCreateWithFlags(&ev3, cudaEventDisableTiming);
        cudaFuncSetAttribute(k_gemm1a, cudaFuncAttributeMaxDynamicSharedMemorySize, GSMEM1);
        cudaFuncSetAttribute(k_refine, cudaFuncAttributeMaxDynamicSharedMemorySize, GSMEM4);
        cudaFuncSetAttribute(k_gemm3t, cudaFuncAttributeMaxDynamicSharedMemorySize, GSMEM4);
    }

    // fork: A m-plane split + MLP chain on s1
    cudaEventRecord(ev0, 0);
    cudaStreamWaitEvent(s1, ev0, 0);
    k_splitAm<<<(BB * SS * KIN / 4) / 256, 256, 0, s1>>>(act);
    k_initMask<<<(BB * NIN + 255) / 256, 256, 0, s1>>>();
    k_scatter<<<(BB * KIN + 255) / 256, 256, 0, s1>>>(sidx);
    k_hidden<<<HID, 256, 0, s1>>>(w1, b1);
    k_relsig<<<NP / 8, 256, 0, s1>>>(w2, b2);
    cudaEventRecord(ev1, s1);

    // main chain
    k_initScore<<<(BB * NP + 255) / 256, 256>>>();
    k_splitAh<<<(BB * SS * KIN / 4) / 256, 256>>>(act);
    k_gatherBh<<<NP, 256>>>(cw, sidx);
    k_gemm1a<<<dim3(NP / 256, SS / 128, BB), 256, GSMEM1>>>();

    // join: needs g_sig (+ splitAm before refine)
    cudaStreamWaitEvent(0, ev1, 0);
    k_topk512<<<BB, 1024>>>();
    k_gatherB512<<<BB * NC, 256>>>(cw, sidx);
    k_refine<<<dim3(NC / 128, SS / 128, BB), 256, GSMEM4>>>();
    k_rescore<<<BB, 512>>>();

    // fork: projsplit on s1, compact on main
    cudaEventRecord(ev2, 0);
    cudaStreamWaitEvent(s1, ev2, 0);
    k_projsplit<<<dim3(KSEL / 32, DM / 32, BB), dim3(32, 8), 0, s1>>>(proj);
    cudaEventRecord(ev3, s1);
    k_compact<<<BB * SS / 8, 256>>>();
    cudaStreamWaitEvent(0, ev3, 0);

    k_gemm3t<<<dim3(DM / 128, SS / 128, BB), 256, GSMEM4>>>(out);
}

// round 7
// speedup vs baseline: 1.5445x; 1.5445x over previous
#include <cuda_runtime.h>
#include <cuda_bf16.h>

#define BB   8
#define SS   2048
#define KIN  512
#define NIN  2048
#define NP   4096
#define HID  4096
#define DM   1024
#define KSEL 256
#define NC   512

typedef unsigned long long ull;
typedef unsigned int u32;

// ---------------- scratch ----------------
__device__ __align__(256) __nv_bfloat16 g_Asp[(size_t)BB * 2 * SS * KIN];
__device__ __align__(256) __nv_bfloat16 g_Bh [(size_t)BB * NP * KIN];
__device__ __align__(256) __nv_bfloat16 g_Bc [(size_t)BB * 2 * NC * KIN];
__device__ __align__(256) __nv_bfloat16 g_PC [(size_t)BB * 2 * SS * NC];
__device__ __align__(256) __nv_bfloat16 g_PA [(size_t)BB * 2 * SS * KSEL];
__device__ __align__(256) __nv_bfloat16 g_Pr [(size_t)BB * 2 * DM * KSEL];
__device__ float    g_mask[BB * NIN];
__device__ float    g_h[BB * HID];
__device__ float    g_sig[BB * NP];
__device__ unsigned g_scoreEnc[BB * NP];
__device__ unsigned g_scoreEnc2[BB * NC];
__device__ int      g_pidx512[BB * NC];
__device__ int      g_pidx[BB * KSEL];
__device__ int      g_cmap[BB * KSEL];

// ---------------- helpers ----------------
__device__ __forceinline__ unsigned fenc(float f) {
    unsigned u = __float_as_uint(f);
    return (u & 0x80000000u) ? ~u : (u | 0x80000000u);
}
__device__ __forceinline__ float fdec(unsigned u) {
    return __uint_as_float((u & 0x80000000u) ? (u & 0x7fffffffu) : ~u);
}
__device__ __forceinline__ float gelu_f(float x) {
    return 0.5f * x * (1.0f + erff(x * 0.70710678118654752f));
}
__device__ __forceinline__ u32 smem_u32(const void* p) {
    u32 a; asm("{ .reg .u64 t; cvta.to.shared.u64 t, %1; cvt.u32.u64 %0, t; }" : "=r"(a) : "l"(p));
    return a;
}
__device__ __forceinline__ void split2(float a, __nv_bfloat16& h, __nv_bfloat16& m) {
    h = __float2bfloat16(a);
    m = __float2bfloat16(a - __bfloat162float(h));
}

// ---------------- mma.sync / ldmatrix / cp.async ----------------
__device__ __forceinline__ void mma16816(float* d, const u32* a, u32 b0, u32 b1) {
    asm volatile("mma.sync.aligned.m16n8k16.row.col.f32.bf16.bf16.f32 "
        "{%0,%1,%2,%3}, {%4,%5,%6,%7}, {%8,%9}, {%0,%1,%2,%3};"
        : "+f"(d[0]), "+f"(d[1]), "+f"(d[2]), "+f"(d[3])
        : "r"(a[0]), "r"(a[1]), "r"(a[2]), "r"(a[3]), "r"(b0), "r"(b1));
}
__device__ __forceinline__ void ldsm4(u32* r, u32 addr) {
    asm volatile("ldmatrix.sync.aligned.m8n8.x4.shared.b16 {%0,%1,%2,%3}, [%4];"
        : "=r"(r[0]), "=r"(r[1]), "=r"(r[2]), "=r"(r[3]) : "r"(addr));
}
__device__ __forceinline__ void cpasync16(u32 dst, const void* src) {
    asm volatile("cp.async.cg.shared.global [%0], [%1], 16;" :: "r"(dst), "l"(src));
}
#define CP_COMMIT() asm volatile("cp.async.commit_group;" ::: "memory")
#define CP_WAIT(n)  asm volatile("cp.async.wait_group %0;" :: "n"(n) : "memory")

#define RPAD   80
#define PLANE  (128 * RPAD)          // 10240
#define BPLANE (256 * RPAD)          // 20480
#define STGB4  (4 * PLANE)           // refine/gemm3t stage: 40960
#define GSMEM4 (2 * STGB4)           // 81920 -> 2 CTAs/SM
#define STG1   (PLANE + BPLANE)      // gemm1a stage: 30720
#define GSMEM1 (2 * STG1)            // 61440 -> 2-3 CTAs/SM

// ---------------- init kernels ----------------
__global__ void k_initMask() {
    int t = blockIdx.x * blockDim.x + threadIdx.x;
    if (t < BB * NIN) g_mask[t] = 0.0f;
}
__global__ void k_initScore() {
    int t = blockIdx.x * blockDim.x + threadIdx.x;
    if (t < BB * NP)  g_scoreEnc[t] = 0u;
    if (t < BB * NC)  g_scoreEnc2[t] = 0u;
}
__global__ void k_scatter(const int* __restrict__ sidx) {
    int t = blockIdx.x * blockDim.x + threadIdx.x;
    if (t < BB * KIN) {
        int b = t >> 9;
        g_mask[b * NIN + sidx[t]] = 1.0f;
    }
}

// ---------------- split A planes ----------------
union B4U { __nv_bfloat16 h[4]; ull u; };
union B2U { __nv_bfloat16 h[2]; u32 u; };

__global__ void k_splitAh(const float* __restrict__ act) {
    size_t t = (size_t)blockIdx.x * 256 + threadIdx.x;
    size_t bs = t >> 7;
    int k4 = (int)(t & 127);
    int b = (int)(bs >> 11), s = (int)(bs & 2047);
    float4 v = ((const float4*)act)[t];
    float vv[4] = { v.x, v.y, v.z, v.w };
    B4U hh;
#pragma unroll
    for (int i = 0; i < 4; i++) hh.h[i] = __float2bfloat16(vv[i]);
    *(ull*)(g_Asp + ((size_t)(b * 2) * SS + s) * KIN + k4 * 4) = hh.u;
}

__global__ void k_splitAm(const float* __restrict__ act) {
    size_t t = (size_t)blockIdx.x * 256 + threadIdx.x;
    size_t bs = t >> 7;
    int k4 = (int)(t & 127);
    int b = (int)(bs >> 11), s = (int)(bs & 2047);
    float4 v = ((const float4*)act)[t];
    float vv[4] = { v.x, v.y, v.z, v.w };
    B4U mm;
#pragma unroll
    for (int i = 0; i < 4; i++) {
        __nv_bfloat16 h = __float2bfloat16(vv[i]);
        mm.h[i] = __float2bfloat16(vv[i] - __bfloat162float(h));
    }
    *(ull*)(g_Asp + ((size_t)(b * 2 + 1) * SS + s) * KIN + k4 * 4) = mm.u;
}

// ---------------- gather B h-plane (full 4096 rows) ----------------
__global__ void k_gatherBh(const float* __restrict__ cw, const int* __restrict__ sidx) {
    __shared__ float row[NIN];
    __shared__ int sidxS[BB * KIN];    // 16 KB
    int p = blockIdx.x, tid = threadIdx.x;
    for (int i = tid; i < NIN; i += 256) row[i] = cw[(size_t)p * NIN + i];
    for (int i = tid; i < BB * KIN / 4; i += 256)
        ((int4*)sidxS)[i] = ((const int4*)sidx)[i];
    __syncthreads();
    int k = tid * 2;
#pragma unroll 1
    for (int b = 0; b < BB; b++) {
        int i0 = sidxS[b * KIN + k], i1 = sidxS[b * KIN + k + 1];
        B2U hh;
        hh.h[0] = __float2bfloat16(row[i0]);
        hh.h[1] = __float2bfloat16(row[i1]);
        *(u32*)(g_Bh + ((size_t)b * NP + p) * KIN + k) = hh.u;
    }
}

// ---------------- gather B splits for 512 candidates ----------------
__global__ void k_gatherB512(const float* __restrict__ cw, const int* __restrict__ sidx) {
    __shared__ float row[NIN];
    int blk = blockIdx.x;
    int b = blk >> 9, j = blk & (NC - 1);
    int tid = threadIdx.x;
    int p = g_pidx512[b * NC + j];
    for (int i = tid; i < NIN; i += 256) row[i] = cw[(size_t)p * NIN + i];
    __syncthreads();
    int k = tid * 2;
    int i0 = sidx[b * KIN + k], i1 = sidx[b * KIN + k + 1];
    B2U hh, mm;
    split2(row[i0], hh.h[0], mm.h[0]);
    split2(row[i1], hh.h[1], mm.h[1]);
    const size_t PL = (size_t)NC * KIN;
    size_t base = ((size_t)(b * 2) * NC + j) * KIN + k;
    *(u32*)(g_Bc + base)      = hh.u;
    *(u32*)(g_Bc + base + PL) = mm.u;
}

// ---------------- K1a: approx score GEMM, 128x256 tile, k-slab 32 ----------------
__global__ __launch_bounds__(256)
void k_gemm1a() {
    extern __shared__ char smem[];
    const u32 sbase = smem_u32(smem);
    const int tid = threadIdx.x;
    const int wid = tid >> 5, lid = tid & 31;
    const int wm = wid & 3, wn = wid >> 2;       // warp tile 32 x 128
    const int b  = blockIdx.z;
    const int p0 = blockIdx.x * 256;
    const int s0 = blockIdx.y * 128;

    float acc[2][16][4];
#pragma unroll
    for (int i = 0; i < 2; i++)
#pragma unroll
        for (int j = 0; j < 16; j++)
#pragma unroll
            for (int r = 0; r < 4; r++) acc[i][j][r] = 0.0f;

    auto load_stage = [&](int ks, int buf) {
        const int k0 = ks * 32;
        u32 sgA = sbase + buf * STG1;
        u32 sgB = sgA + PLANE;
#pragma unroll
        for (int i = 0; i < 2; i++) {
            int idx = tid + i * 256;
            int r = idx >> 2, c = idx & 3;
            const __nv_bfloat16* g = g_Asp + ((size_t)(b * 2) * SS + s0 + r) * KIN + k0 + c * 8;
            cpasync16(sgA + r * RPAD + c * 16, g);
        }
#pragma unroll
        for (int i = 0; i < 4; i++) {
            int idx = tid + i * 256;
            int r = idx >> 2, c = idx & 3;
            const __nv_bfloat16* g = g_Bh + ((size_t)b * NP + p0 + r) * KIN + k0 + c * 8;
            cpasync16(sgB + r * RPAD + c * 16, g);
        }
    };

    const u32 aoff = (u32)((wm * 32 + (lid & 15)) * RPAD + (lid >> 4) * 16);
    const u32 boff = (u32)((wn * 128 + (lid & 15)) * RPAD + (lid >> 4) * 16);

    load_stage(0, 0); CP_COMMIT();

#pragma unroll 1
    for (int ks = 0; ks < KIN / 32; ks++) {
        int buf = ks & 1;
        if (ks < KIN / 32 - 1) { load_stage(ks + 1, buf ^ 1); CP_COMMIT(); CP_WAIT(1); }
        else                   { CP_WAIT(0); }
        __syncthreads();
        u32 sA = sbase + buf * STG1;
        u32 sB = sA + PLANE;
#pragma unroll
        for (int kk = 0; kk < 2; kk++) {
            u32 ah[2][4];
#pragma unroll
            for (int mt = 0; mt < 2; mt++)
                ldsm4(ah[mt], sA + aoff + mt * (16 * RPAD) + kk * 32);
            u32 bh[8][4];
#pragma unroll
            for (int q = 0; q < 8; q++)
                ldsm4(bh[q], sB + boff + q * (16 * RPAD) + kk * 32);
#pragma unroll
            for (int mt = 0; mt < 2; mt++)
#pragma unroll
                for (int q = 0; q < 8; q++) {
                    mma16816(acc[mt][2 * q],     ah[mt], bh[q][0], bh[q][2]);
                    mma16816(acc[mt][2 * q + 1], ah[mt], bh[q][1], bh[q][3]);
                }
        }
        __syncthreads();
    }

    u32* scol = (u32*)smem;
    if (tid < 256) scol[tid] = 0u;
    __syncthreads();
#pragma unroll
    for (int nt = 0; nt < 16; nt++) {
        float m0 = fmaxf(fmaxf(acc[0][nt][0], acc[0][nt][2]), fmaxf(acc[1][nt][0], acc[1][nt][2]));
        float m1 = fmaxf(fmaxf(acc[0][nt][1], acc[0][nt][3]), fmaxf(acc[1][nt][1], acc[1][nt][3]));
#pragma unroll
        for (int mk = 4; mk < 32; mk <<= 1) {
            m0 = fmaxf(m0, __shfl_xor_sync(0xffffffffu, m0, mk));
            m1 = fmaxf(m1, __shfl_xor_sync(0xffffffffu, m1, mk));
        }
        if (lid < 4) {
            atomicMax(&scol[wn * 128 + nt * 8 + 2 * lid],     fenc(m0));
            atomicMax(&scol[wn * 128 + nt * 8 + 2 * lid + 1], fenc(m1));
        }
    }
    __syncthreads();
    if (tid < 256) atomicMax(&g_scoreEnc[b * NP + p0 + tid], scol[tid]);
}

// ---------------- K2: hidden MLP ----------------
__global__ void k_hidden(const float* __restrict__ w1, const float* __restrict__ b1) {
    int j = blockIdx.x;
    int tid = threadIdx.x;
    const float* wr = w1 + (size_t)j * NIN;
    float acc[BB];
#pragma unroll
    for (int b = 0; b < BB; b++) acc[b] = 0.0f;
    for (int n = tid; n < NIN; n += 256) {
        float w = wr[n];
#pragma unroll
        for (int b = 0; b < BB; b++) acc[b] += w * g_mask[b * NIN + n];
    }
    __shared__ float red[BB][256];
#pragma unroll
    for (int b = 0; b < BB; b++) red[b][tid] = acc[b];
    __syncthreads();
    for (int s1 = 128; s1 > 0; s1 >>= 1) {
        if (tid < s1) {
#pragma unroll
            for (int b = 0; b < BB; b++) red[b][tid] += red[b][tid + s1];
        }
        __syncthreads();
    }
    if (tid < BB) g_h[tid * HID + j] = gelu_f(red[tid][0] + b1[j]);
}

// ---------------- K3a: relevance -> sigmoid (float4) ----------------
__global__ void k_relsig(const float* __restrict__ w2, const float* __restrict__ b2) {
    int warp = threadIdx.x >> 5, lane = threadIdx.x & 31;
    int p = blockIdx.x * 8 + warp;
    const float4* wr = (const float4*)(w2 + (size_t)p * HID);
    float acc[BB];
#pragma unroll
    for (int b = 0; b < BB; b++) acc[b] = 0.0f;
#pragma unroll 4
    for (int j = lane; j < HID / 4; j += 32) {
        float4 w = wr[j];
#pragma unroll
        for (int b = 0; b < BB; b++) {
            float4 h = ((const float4*)(g_h + b * HID))[j];
            acc[b] += w.x * h.x + w.y * h.y + w.z * h.z + w.w * h.w;
        }
    }
#pragma unroll
    for (int o = 16; o > 0; o >>= 1)
#pragma unroll
        for (int b = 0; b < BB; b++) acc[b] += __shfl_down_sync(0xffffffffu, acc[b], o);
    if (lane == 0) {
#pragma unroll
        for (int b = 0; b < BB; b++) {
            float rel = acc[b] + b2[p];
            g_sig[b * NP + p] = 1.0f / (1.0f + expf(-rel));
        }
    }
}

// ---------------- K4: approx top-512 (score inline) ----------------
__global__ void k_topk512() {
    __shared__ ull key[NP];
    int b = blockIdx.x, tid = threadIdx.x;
    for (int i = tid; i < NP; i += 1024) {
        float sc = gelu_f(fdec(g_scoreEnc[b * NP + i])) * g_sig[b * NP + i];
        key[i] = ((ull)fenc(sc) << 32) | (unsigned)i;
    }
    __syncthreads();
    for (int k = 2; k <= NP; k <<= 1) {
        for (int j = k >> 1; j > 0; j >>= 1) {
            for (int i = tid; i < NP; i += 1024) {
                int ix = i ^ j;
                if (ix > i) {
                    ull x = key[i], y = key[ix];
                    bool desc = ((i & k) == 0);
                    if (desc ? (x < y) : (x > y)) { key[i] = y; key[ix] = x; }
                }
            }
            __syncthreads();
        }
    }
    if (tid < NC) g_pidx512[b * NC + tid] = (int)(key[tid] & 0xffffffffu);
}

// ---------------- K5: refine — exact 3-pass z for 512 cands, k-slab 32 ----------------
__global__ __launch_bounds__(256)
void k_refine() {
    extern __shared__ char smem[];
    const u32 sbase = smem_u32(smem);
    const int tid = threadIdx.x;
    const int wid = tid >> 5, lid = tid & 31;
    const int wm = wid & 3, wn = wid >> 2;
    const int b  = blockIdx.z;
    const int n0 = blockIdx.x * 128;
    const int s0 = blockIdx.y * 128;

    float acc[2][8][4];
#pragma unroll
    for (int i = 0; i < 2; i++)
#pragma unroll
        for (int j = 0; j < 8; j++)
#pragma unroll
            for (int r = 0; r < 4; r++) acc[i][j][r] = 0.0f;

    auto load_stage = [&](int ks, int buf) {
        const int k0 = ks * 32;
        u32 sg = sbase + buf * STGB4;
#pragma unroll
        for (int i = 0; i < 4; i++) {
            int idx = tid + i * 256;
            int sp = idx >> 9, rem = idx & 511;
            int r = rem >> 2, c = rem & 3;
            const __nv_bfloat16* g = g_Asp + ((size_t)(b * 2 + sp) * SS + s0 + r) * KIN + k0 + c * 8;
            cpasync16(sg + sp * PLANE + r * RPAD + c * 16, g);
        }
#pragma unroll
        for (int i = 0; i < 4; i++) {
            int idx = tid + i * 256;
            int sp = idx >> 9, rem = idx & 511;
            int r = rem >> 2, c = rem & 3;
            const __nv_bfloat16* g = g_Bc + ((size_t)(b * 2 + sp) * NC + n0 + r) * KIN + k0 + c * 8;
            cpasync16(sg + 2 * PLANE + sp * PLANE + r * RPAD + c * 16, g);
        }
    };

    const u32 aoff = (u32)((wm * 32 + (lid & 15)) * RPAD + (lid >> 4) * 16);
    const u32 boff = (u32)((wn * 64 + (lid & 15)) * RPAD + (lid >> 4) * 16);

    load_stage(0, 0); CP_COMMIT();

#pragma unroll 1
    for (int ks = 0; ks < KIN / 32; ks++) {
        int buf = ks & 1;
        if (ks < KIN / 32 - 1) { load_stage(ks + 1, buf ^ 1); CP_COMMIT(); CP_WAIT(1); }
        else                   { CP_WAIT(0); }
        __syncthreads();
        u32 sA = sbase + buf * STGB4;
        u32 sB = sA + 2 * PLANE;
#pragma unroll
        for (int kk = 0; kk < 2; kk++) {
            u32 ah[2][4], am[2][4];
#pragma unroll
            for (int mt = 0; mt < 2; mt++) {
                ldsm4(ah[mt], sA + aoff + mt * (16 * RPAD) + kk * 32);
                ldsm4(am[mt], sA + PLANE + aoff + mt * (16 * RPAD) + kk * 32);
            }
            u32 bh[4][4], bm[4][4];
#pragma unroll
            for (int nt2 = 0; nt2 < 4; nt2++) {
                ldsm4(bh[nt2], sB + boff + nt2 * (16 * RPAD) + kk * 32);
                ldsm4(bm[nt2], sB + PLANE + boff + nt2 * (16 * RPAD) + kk * 32);
            }
#pragma unroll
            for (int mt = 0; mt < 2; mt++)
#pragma unroll
                for (int nt2 = 0; nt2 < 4; nt2++) {
                    mma16816(acc[mt][2 * nt2],     ah[mt], bh[nt2][0], bh[nt2][2]);
                    mma16816(acc[mt][2 * nt2 + 1], ah[mt], bh[nt2][1], bh[nt2][3]);
                    mma16816(acc[mt][2 * nt2],     ah[mt], bm[nt2][0], bm[nt2][2]);
                    mma16816(acc[mt][2 * nt2 + 1], ah[mt], bm[nt2][1], bm[nt2][3]);
                    mma16816(acc[mt][2 * nt2],     am[mt], bh[nt2][0], bh[nt2][2]);
                    mma16816(acc[mt][2 * nt2 + 1], am[mt], bh[nt2][1], bh[nt2][3]);
                }
        }
        __syncthreads();
    }

    u32* scol = (u32*)smem;
    if (tid < 128) scol[tid] = 0u;
    __syncthreads();

    const size_t PL = (size_t)SS * NC;
#pragma unroll
    for (int mt = 0; mt < 2; mt++)
#pragma unroll
        for (int nt = 0; nt < 8; nt++) {
            int row = s0 + wm * 32 + mt * 16 + (lid >> 2);
            int col = n0 + wn * 64 + nt * 8 + 2 * (lid & 3);
            float g0 = gelu_f(acc[mt][nt][0]), g1 = gelu_f(acc[mt][nt][1]);
            float g2 = gelu_f(acc[mt][nt][2]), g3 = gelu_f(acc[mt][nt][3]);
            B2U h01, m01, h23, m23;
            split2(g0, h01.h[0], m01.h[0]); split2(g1, h01.h[1], m01.h[1]);
            split2(g2, h23.h[0], m23.h[0]); split2(g3, h23.h[1], m23.h[1]);
            size_t base = ((size_t)(b * 2) * SS + row) * NC + col;
            *(u32*)(g_PC + base)               = h01.u;
            *(u32*)(g_PC + base + PL)          = m01.u;
            *(u32*)(g_PC + base + 8 * NC)      = h23.u;
            *(u32*)(g_PC + base + PL + 8 * NC) = m23.u;
        }
#pragma unroll
    for (int nt = 0; nt < 8; nt++) {
        float m0 = fmaxf(fmaxf(acc[0][nt][0], acc[0][nt][2]), fmaxf(acc[1][nt][0], acc[1][nt][2]));
        float m1 = fmaxf(fmaxf(acc[0][nt][1], acc[0][nt][3]), fmaxf(acc[1][nt][1], acc[1][nt][3]));
#pragma unroll
        for (int mk = 4; mk < 32; mk <<= 1) {
            m0 = fmaxf(m0, __shfl_xor_sync(0xffffffffu, m0, mk));
            m1 = fmaxf(m1, __shfl_xor_sync(0xffffffffu, m1, mk));
        }
        if (lid < 4) {
            atomicMax(&scol[wn * 64 + nt * 8 + 2 * lid],     fenc(m0));
            atomicMax(&scol[wn * 64 + nt * 8 + 2 * lid + 1], fenc(m1));
        }
    }
    __syncthreads();
    if (tid < 128) atomicMax(&g_scoreEnc2[b * NC + n0 + tid], scol[tid]);
}

// ---------------- K6: exact rescore + top-256 ----------------
__global__ void k_rescore() {
    __shared__ ull key[NC];
    int b = blockIdx.x, tid = threadIdx.x;   // 512 threads
    if (tid < NC) {
        float z = fdec(g_scoreEnc2[b * NC + tid]);
        int p = g_pidx512[b * NC + tid];
        float sc = gelu_f(z) * g_sig[b * NP + p];
        key[tid] = ((ull)fenc(sc) << 32) | (unsigned)tid;
    }
    __syncthreads();
    for (int k = 2; k <= NC; k <<= 1) {
        for (int j = k >> 1; j > 0; j >>= 1) {
            int i = tid;
            int ix = i ^ j;
            if (ix > i && i < NC) {
                ull x = key[i], y = key[ix];
                bool desc = ((i & k) == 0);
                if (desc ? (x < y) : (x > y)) { key[i] = y; key[ix] = x; }
            }
            __syncthreads();
        }
    }
    if (tid < KSEL) {
        int slot = (int)(key[tid] & 0xffffffffu);
        g_cmap[b * KSEL + tid] = slot;
        g_pidx[b * KSEL + tid] = g_pidx512[b * NC + slot];
    }
}

// ---------------- K7: compact via smem staging (coalesced) ----------------
__global__ void k_compact() {
    __shared__ __nv_bfloat16 st[2][8][NC];   // 16 KB
    __shared__ int cm[KSEL];
    int blk = blockIdx.x;                    // BB * SS/8 blocks
    int b = blk / (SS / 8);
    int s8 = (blk % (SS / 8)) * 8;
    int tid = threadIdx.x;
    if (tid < KSEL) cm[tid] = g_cmap[b * KSEL + tid];
    const int4* src0 = (const int4*)(g_PC + ((size_t)(b * 2)     * SS + s8) * NC);
    const int4* src1 = (const int4*)(g_PC + ((size_t)(b * 2 + 1) * SS + s8) * NC);
    int4* d0 = (int4*)&st[0][0][0];
    int4* d1 = (int4*)&st[1][0][0];
#pragma unroll
    for (int i = 0; i < 2; i++) {
        int idx = tid + i * 256;
        d0[idx] = src0[idx];
        d1[idx] = src1[idx];
    }
    __syncthreads();
    int j = tid;
    int c = cm[j];
    const size_t PLa = (size_t)SS * KSEL;
#pragma unroll
    for (int r = 0; r < 8; r++) {
        size_t dst = ((size_t)(b * 2) * SS + s8 + r) * KSEL + j;
        g_PA[dst]       = st[0][r][c];
        g_PA[dst + PLa] = st[1][r][c];
    }
}

// ---------------- K8: gather + transpose + split proj rows ----------------
__global__ void k_projsplit(const float* __restrict__ proj) {
    __shared__ float t[32][33];
    __shared__ int pj[32];
    int j0 = blockIdx.x * 32, d0 = blockIdx.y * 32, b = blockIdx.z;
    int tx = threadIdx.x, ty = threadIdx.y;
    if (ty == 0) pj[tx] = g_pidx[b * KSEL + j0 + tx];
    __syncthreads();
#pragma unroll
    for (int i = 0; i < 32; i += 8) {
        int p = pj[ty + i];
        t[ty + i][tx] = proj[(size_t)p * DM + d0 + tx];
    }
    __syncthreads();
    const size_t PL = (size_t)DM * KSEL;
#pragma unroll
    for (int i = 0; i < 32; i += 8) {
        float v = t[tx][ty + i];
        __nv_bfloat16 h, m;
        split2(v, h, m);
        size_t base = ((size_t)(b * 2) * DM + d0 + ty + i) * KSEL + j0 + tx;
        g_Pr[base]      = h;
        g_Pr[base + PL] = m;
    }
}

// ---------------- K9: final GEMM (HMMA 3-pass), k-slab 32 ----------------
__global__ __launch_bounds__(256)
void k_gemm3t(float* __restrict__ out) {
    extern __shared__ char smem[];
    const u32 sbase = smem_u32(smem);
    const int tid = threadIdx.x;
    const int wid = tid >> 5, lid = tid & 31;
    const int wm = wid & 3, wn = wid >> 2;
    const int b  = blockIdx.z;
    const int d0 = blockIdx.x * 128;
    const int s0 = blockIdx.y * 128;

    float acc[2][8][4];
#pragma unroll
    for (int i = 0; i < 2; i++)
#pragma unroll
        for (int j = 0; j < 8; j++)
#pragma unroll
            for (int r = 0; r < 4; r++) acc[i][j][r] = 0.0f;

    auto load_stage = [&](int ks, int buf) {
        const int k0 = ks * 32;
        u32 sg = sbase + buf * STGB4;
#pragma unroll
        for (int i = 0; i < 4; i++) {
            int idx = tid + i * 256;
            int sp = idx >> 9, rem = idx & 511;
            int r = rem >> 2, c = rem & 3;
            const __nv_bfloat16* g = g_PA + ((size_t)(b * 2 + sp) * SS + s0 + r) * KSEL + k0 + c * 8;
            cpasync16(sg + sp * PLANE + r * RPAD + c * 16, g);
        }
#pragma unroll
        for (int i = 0; i < 4; i++) {
            int idx = tid + i * 256;
            int sp = idx >> 9, rem = idx & 511;
            int r = rem >> 2, c = rem & 3;
            const __nv_bfloat16* g = g_Pr + ((size_t)(b * 2 + sp) * DM + d0 + r) * KSEL + k0 + c * 8;
            cpasync16(sg + 2 * PLANE + sp * PLANE + r * RPAD + c * 16, g);
        }
    };

    const u32 aoff = (u32)((wm * 32 + (lid & 15)) * RPAD + (lid >> 4) * 16);
    const u32 boff = (u32)((wn * 64 + (lid & 15)) * RPAD + (lid >> 4) * 16);

    load_stage(0, 0); CP_COMMIT();

#pragma unroll 1
    for (int ks = 0; ks < KSEL / 32; ks++) {
        int buf = ks & 1;
        if (ks < KSEL / 32 - 1) { load_stage(ks + 1, buf ^ 1); CP_COMMIT(); CP_WAIT(1); }
        else                    { CP_WAIT(0); }
        __syncthreads();
        u32 sA = sbase + buf * STGB4;
        u32 sB = sA + 2 * PLANE;
#pragma unroll
        for (int kk = 0; kk < 2; kk++) {
            u32 ah[2][4], am[2][4];
#pragma unroll
            for (int mt = 0; mt < 2; mt++) {
                ldsm4(ah[mt], sA + aoff + mt * (16 * RPAD) + kk * 32);
                ldsm4(am[mt], sA + PLANE + aoff + mt * (16 * RPAD) + kk * 32);
            }
            u32 bh[4][4], bm[4][4];
#pragma unroll
            for (int nt2 = 0; nt2 < 4; nt2++) {
                ldsm4(bh[nt2], sB + boff + nt2 * (16 * RPAD) + kk * 32);
                ldsm4(bm[nt2], sB + PLANE + boff + nt2 * (16 * RPAD) + kk * 32);
            }
#pragma unroll
            for (int mt = 0; mt < 2; mt++)
#pragma unroll
                for (int nt2 = 0; nt2 < 4; nt2++) {
                    mma16816(acc[mt][2 * nt2],     ah[mt], bh[nt2][0], bh[nt2][2]);
                    mma16816(acc[mt][2 * nt2 + 1], ah[mt], bh[nt2][1], bh[nt2][3]);
                    mma16816(acc[mt][2 * nt2],     ah[mt], bm[nt2][0], bm[nt2][2]);
                    mma16816(acc[mt][2 * nt2 + 1], ah[mt], bm[nt2][1], bm[nt2][3]);
                    mma16816(acc[mt][2 * nt2],     am[mt], bh[nt2][0], bh[nt2][2]);
                    mma16816(acc[mt][2 * nt2 + 1], am[mt], bh[nt2][1], bh[nt2][3]);
                }
        }
        __syncthreads();
    }
#pragma unroll
    for (int mt = 0; mt < 2; mt++)
#pragma unroll
        for (int nt = 0; nt < 8; nt++) {
            int row = s0 + wm * 32 + mt * 16 + (lid >> 2);
            int col = d0 + wn * 64 + nt * 8 + 2 * (lid & 3);
            float* po = out + ((size_t)b * SS + row) * DM + col;
            *(float2*)po            = make_float2(acc[mt][nt][0], acc[mt][nt][1]);
            *(float2*)(po + 8 * DM) = make_float2(acc[mt][nt][2], acc[mt][nt][3]);
        }
}

// ---------------- entry (multi-stream fork/join) ----------------
extern "C" void kernel_launch(void* const* d_in, const int* in_sizes, int n_in,
                              void* d_out, int out_size) {
    const float* act  = (const float*)d_in[0];
    const int*   sidx = (const int*)d_in[1];
    int o = (n_in >= 9 && in_sizes[2] == 1) ? 3 : 2;
    const float* cw   = (const float*)d_in[o + 0];
    const float* proj = (const float*)d_in[o + 1];
    const float* w1   = (const float*)d_in[o + 2];
    const float* b1   = (const float*)d_in[o + 3];
    const float* w2   = (const float*)d_in[o + 4];
    const float* b2   = (const float*)d_in[o + 5];
    float* out = (float*)d_out;

    static cudaStream_t s1 = nullptr;
    static cudaEvent_t ev0 = nullptr, ev1 = nullptr, ev2 = nullptr, ev3 = nullptr;
    if (s1 == nullptr) {
        cudaStreamCreateWithFlags(&s1, cudaStreamNonBlocking);
        cudaEventCreateWithFlags(&ev0, cudaEventDisableTiming);
        cudaEventCreateWithFlags(&ev1, cudaEventDisableTiming);
        cudaEventCreateWithFlags(&ev2, cudaEventDisableTiming);
        cudaEventCreateWithFlags(&ev3, cudaEventDisableTiming);
        cudaFuncSetAttribute(k_gemm1a, cudaFuncAttributeMaxDynamicSharedMemorySize, GSMEM1);
        cudaFuncSetAttribute(k_refine, cudaFuncAttributeMaxDynamicSharedMemorySize, GSMEM4);
        cudaFuncSetAttribute(k_gemm3t, cudaFuncAttributeMaxDynamicSharedMemorySize, GSMEM4);
    }

    // fork: A m-plane split + MLP chain on s1
    cudaEventRecord(ev0, 0);
    cudaStreamWaitEvent(s1, ev0, 0);
    k_splitAm<<<(BB * SS * KIN / 4) / 256, 256, 0, s1>>>(act);
    k_initMask<<<(BB * NIN + 255) / 256, 256, 0, s1>>>();
    k_scatter<<<(BB * KIN + 255) / 256, 256, 0, s1>>>(sidx);
    k_hidden<<<HID, 256, 0, s1>>>(w1, b1);
    k_relsig<<<NP / 8, 256, 0, s1>>>(w2, b2);
    cudaEventRecord(ev1, s1);

    // main chain
    k_initScore<<<(BB * NP + 255) / 256, 256>>>();
    k_splitAh<<<(BB * SS * KIN / 4) / 256, 256>>>(act);
    k_gatherBh<<<NP, 256>>>(cw, sidx);
    k_gemm1a<<<dim3(NP / 256, SS / 128, BB), 256, GSMEM1>>>();

    // join
    cudaStreamWaitEvent(0, ev1, 0);
    k_topk512<<<BB, 1024>>>();
    k_gatherB512<<<BB * NC, 256>>>(cw, sidx);
    k_refine<<<dim3(NC / 128, SS / 128, BB), 256, GSMEM4>>>();
    k_rescore<<<BB, 512>>>();

    // fork: projsplit on s1, compact on main
    cudaEventRecord(ev2, 0);
    cudaStreamWaitEvent(s1, ev2, 0);
    k_projsplit<<<dim3(KSEL / 32, DM / 32, BB), dim3(32, 8), 0, s1>>>(proj);
    cudaEventRecord(ev3, s1);
    k_compact<<<BB * SS / 8, 256>>>();
    cudaStreamWaitEvent(0, ev3, 0);

    k_gemm3t<<<dim3(DM / 128, SS / 128, BB), 256, GSMEM4>>>(out);
}

// round 8
// speedup vs baseline: 1.5533x; 1.0058x over previous
#include <cuda_runtime.h>
#include <cuda_bf16.h>

#define BB   8
#define SS   2048
#define KIN  512
#define NIN  2048
#define NP   4096
#define HID  4096
#define DM   1024
#define KSEL 256
#define NC   384     // refine candidate count (margin 128 ranks ~ 21 sigma)
#define NCP  512     // padded for bitonic

typedef unsigned long long ull;
typedef unsigned int u32;

// ---------------- scratch ----------------
__device__ __align__(256) __nv_bfloat16 g_Asp[(size_t)BB * 2 * SS * KIN];
__device__ __align__(256) __nv_bfloat16 g_Bh [(size_t)BB * NP * KIN];
__device__ __align__(256) __nv_bfloat16 g_Bc [(size_t)BB * 2 * NC * KIN];
__device__ __align__(256) __nv_bfloat16 g_PC [(size_t)BB * 2 * SS * NC];
__device__ __align__(256) __nv_bfloat16 g_PA [(size_t)BB * 2 * SS * KSEL];
__device__ __align__(256) __nv_bfloat16 g_Pr [(size_t)BB * 2 * DM * KSEL];
__device__ float    g_mask[BB * NIN];
__device__ float    g_h[BB * HID];
__device__ float    g_sig[BB * NP];
__device__ unsigned g_scoreEnc[BB * NP];
__device__ unsigned g_scoreEnc2[BB * NC];
__device__ int      g_pidx512[BB * NC];
__device__ int      g_pidx[BB * KSEL];
__device__ int      g_cmap[BB * KSEL];

// ---------------- helpers ----------------
__device__ __forceinline__ unsigned fenc(float f) {
    unsigned u = __float_as_uint(f);
    return (u & 0x80000000u) ? ~u : (u | 0x80000000u);
}
__device__ __forceinline__ float fdec(unsigned u) {
    return __uint_as_float((u & 0x80000000u) ? (u & 0x7fffffffu) : ~u);
}
__device__ __forceinline__ float gelu_f(float x) {
    return 0.5f * x * (1.0f + erff(x * 0.70710678118654752f));
}
__device__ __forceinline__ u32 smem_u32(const void* p) {
    u32 a; asm("{ .reg .u64 t; cvta.to.shared.u64 t, %1; cvt.u32.u64 %0, t; }" : "=r"(a) : "l"(p));
    return a;
}
__device__ __forceinline__ void split2(float a, __nv_bfloat16& h, __nv_bfloat16& m) {
    h = __float2bfloat16(a);
    m = __float2bfloat16(a - __bfloat162float(h));
}

// ---------------- mma.sync / ldmatrix / cp.async ----------------
__device__ __forceinline__ void mma16816(float* d, const u32* a, u32 b0, u32 b1) {
    asm volatile("mma.sync.aligned.m16n8k16.row.col.f32.bf16.bf16.f32 "
        "{%0,%1,%2,%3}, {%4,%5,%6,%7}, {%8,%9}, {%0,%1,%2,%3};"
        : "+f"(d[0]), "+f"(d[1]), "+f"(d[2]), "+f"(d[3])
        : "r"(a[0]), "r"(a[1]), "r"(a[2]), "r"(a[3]), "r"(b0), "r"(b1));
}
__device__ __forceinline__ void ldsm4(u32* r, u32 addr) {
    asm volatile("ldmatrix.sync.aligned.m8n8.x4.shared.b16 {%0,%1,%2,%3}, [%4];"
        : "=r"(r[0]), "=r"(r[1]), "=r"(r[2]), "=r"(r[3]) : "r"(addr));
}
__device__ __forceinline__ void cpasync16(u32 dst, const void* src) {
    asm volatile("cp.async.cg.shared.global [%0], [%1], 16;" :: "r"(dst), "l"(src));
}
#define CP_COMMIT() asm volatile("cp.async.commit_group;" ::: "memory")
#define CP_WAIT(n)  asm volatile("cp.async.wait_group %0;" :: "n"(n) : "memory")

#define RPAD   80
#define PLANE  (128 * RPAD)          // 10240
#define BPLANE (256 * RPAD)          // 20480
#define STGB4  (4 * PLANE)           // refine/gemm3t stage: 40960
#define GSMEM4 (2 * STGB4)           // 81920 -> 2 CTAs/SM
#define STG1   (PLANE + BPLANE)      // gemm1a stage: 30720
#define GSMEM1 (3 * STG1)            // 92160, 3-stage (gemm1a is reg-bound to 1 CTA/SM)

// ---------------- init kernels ----------------
__global__ void k_initMask() {
    int t = blockIdx.x * blockDim.x + threadIdx.x;
    if (t < BB * NIN) g_mask[t] = 0.0f;
}
__global__ void k_initScore() {
    int t = blockIdx.x * blockDim.x + threadIdx.x;
    if (t < BB * NP)  g_scoreEnc[t] = 0u;
    if (t < BB * NC)  g_scoreEnc2[t] = 0u;
}
__global__ void k_scatter(const int* __restrict__ sidx) {
    int t = blockIdx.x * blockDim.x + threadIdx.x;
    if (t < BB * KIN) {
        int b = t >> 9;
        g_mask[b * NIN + sidx[t]] = 1.0f;
    }
}

// ---------------- split A planes ----------------
union B4U { __nv_bfloat16 h[4]; ull u; };
union B2U { __nv_bfloat16 h[2]; u32 u; };

__global__ void k_splitAh(const float* __restrict__ act) {
    size_t t = (size_t)blockIdx.x * 256 + threadIdx.x;
    size_t bs = t >> 7;
    int k4 = (int)(t & 127);
    int b = (int)(bs >> 11), s = (int)(bs & 2047);
    float4 v = ((const float4*)act)[t];
    float vv[4] = { v.x, v.y, v.z, v.w };
    B4U hh;
#pragma unroll
    for (int i = 0; i < 4; i++) hh.h[i] = __float2bfloat16(vv[i]);
    *(ull*)(g_Asp + ((size_t)(b * 2) * SS + s) * KIN + k4 * 4) = hh.u;
}

__global__ void k_splitAm(const float* __restrict__ act) {
    size_t t = (size_t)blockIdx.x * 256 + threadIdx.x;
    size_t bs = t >> 7;
    int k4 = (int)(t & 127);
    int b = (int)(bs >> 11), s = (int)(bs & 2047);
    float4 v = ((const float4*)act)[t];
    float vv[4] = { v.x, v.y, v.z, v.w };
    B4U mm;
#pragma unroll
    for (int i = 0; i < 4; i++) {
        __nv_bfloat16 h = __float2bfloat16(vv[i]);
        mm.h[i] = __float2bfloat16(vv[i] - __bfloat162float(h));
    }
    *(ull*)(g_Asp + ((size_t)(b * 2 + 1) * SS + s) * KIN + k4 * 4) = mm.u;
}

// ---------------- gather B h-plane (full 4096 rows) ----------------
__global__ void k_gatherBh(const float* __restrict__ cw, const int* __restrict__ sidx) {
    __shared__ float row[NIN];
    __shared__ int sidxS[BB * KIN];    // 16 KB
    int p = blockIdx.x, tid = threadIdx.x;
    for (int i = tid; i < NIN; i += 256) row[i] = cw[(size_t)p * NIN + i];
    for (int i = tid; i < BB * KIN / 4; i += 256)
        ((int4*)sidxS)[i] = ((const int4*)sidx)[i];
    __syncthreads();
    int k = tid * 2;
#pragma unroll 1
    for (int b = 0; b < BB; b++) {
        int i0 = sidxS[b * KIN + k], i1 = sidxS[b * KIN + k + 1];
        B2U hh;
        hh.h[0] = __float2bfloat16(row[i0]);
        hh.h[1] = __float2bfloat16(row[i1]);
        *(u32*)(g_Bh + ((size_t)b * NP + p) * KIN + k) = hh.u;
    }
}

// ---------------- gather B splits for NC candidates ----------------
__global__ void k_gatherBc(const float* __restrict__ cw, const int* __restrict__ sidx) {
    __shared__ float row[NIN];
    int blk = blockIdx.x;              // b * NC + j
    int b = blk / NC, j = blk % NC;
    int tid = threadIdx.x;
    int p = g_pidx512[b * NC + j];
    for (int i = tid; i < NIN; i += 256) row[i] = cw[(size_t)p * NIN + i];
    __syncthreads();
    int k = tid * 2;
    int i0 = sidx[b * KIN + k], i1 = sidx[b * KIN + k + 1];
    B2U hh, mm;
    split2(row[i0], hh.h[0], mm.h[0]);
    split2(row[i1], hh.h[1], mm.h[1]);
    const size_t PL = (size_t)NC * KIN;
    size_t base = ((size_t)(b * 2) * NC + j) * KIN + k;
    *(u32*)(g_Bc + base)      = hh.u;
    *(u32*)(g_Bc + base + PL) = mm.u;
}

// ---------------- K1a: approx score GEMM, 128x256 tile, 3-stage ----------------
__global__ __launch_bounds__(256)
void k_gemm1a() {
    extern __shared__ char smem[];
    const u32 sbase = smem_u32(smem);
    const int tid = threadIdx.x;
    const int wid = tid >> 5, lid = tid & 31;
    const int wm = wid & 3, wn = wid >> 2;       // warp tile 32 x 128
    const int b  = blockIdx.z;
    const int p0 = blockIdx.x * 256;
    const int s0 = blockIdx.y * 128;

    float acc[2][16][4];
#pragma unroll
    for (int i = 0; i < 2; i++)
#pragma unroll
        for (int j = 0; j < 16; j++)
#pragma unroll
            for (int r = 0; r < 4; r++) acc[i][j][r] = 0.0f;

    auto load_stage = [&](int ks, int buf) {
        const int k0 = ks * 32;
        u32 sgA = sbase + buf * STG1;
        u32 sgB = sgA + PLANE;
#pragma unroll
        for (int i = 0; i < 2; i++) {
            int idx = tid + i * 256;
            int r = idx >> 2, c = idx & 3;
            const __nv_bfloat16* g = g_Asp + ((size_t)(b * 2) * SS + s0 + r) * KIN + k0 + c * 8;
            cpasync16(sgA + r * RPAD + c * 16, g);
        }
#pragma unroll
        for (int i = 0; i < 4; i++) {
            int idx = tid + i * 256;
            int r = idx >> 2, c = idx & 3;
            const __nv_bfloat16* g = g_Bh + ((size_t)b * NP + p0 + r) * KIN + k0 + c * 8;
            cpasync16(sgB + r * RPAD + c * 16, g);
        }
    };

    const u32 aoff = (u32)((wm * 32 + (lid & 15)) * RPAD + (lid >> 4) * 16);
    const u32 boff = (u32)((wn * 128 + (lid & 15)) * RPAD + (lid >> 4) * 16);

    const int NKS = KIN / 32;   // 16
    load_stage(0, 0); CP_COMMIT();
    load_stage(1, 1); CP_COMMIT();

#pragma unroll 1
    for (int ks = 0; ks < NKS; ks++) {
        int buf = ks % 3;
        if (ks + 2 < NKS) { load_stage(ks + 2, (ks + 2) % 3); CP_COMMIT(); CP_WAIT(2); }
        else if (ks + 1 < NKS) { CP_WAIT(1); }
        else { CP_WAIT(0); }
        __syncthreads();
        u32 sA = sbase + buf * STG1;
        u32 sB = sA + PLANE;
#pragma unroll
        for (int kk = 0; kk < 2; kk++) {
            u32 ah[2][4];
#pragma unroll
            for (int mt = 0; mt < 2; mt++)
                ldsm4(ah[mt], sA + aoff + mt * (16 * RPAD) + kk * 32);
            u32 bh[8][4];
#pragma unroll
            for (int q = 0; q < 8; q++)
                ldsm4(bh[q], sB + boff + q * (16 * RPAD) + kk * 32);
#pragma unroll
            for (int mt = 0; mt < 2; mt++)
#pragma unroll
                for (int q = 0; q < 8; q++) {
                    mma16816(acc[mt][2 * q],     ah[mt], bh[q][0], bh[q][2]);
                    mma16816(acc[mt][2 * q + 1], ah[mt], bh[q][1], bh[q][3]);
                }
        }
        __syncthreads();
    }

    u32* scol = (u32*)smem;
    if (tid < 256) scol[tid] = 0u;
    __syncthreads();
#pragma unroll
    for (int nt = 0; nt < 16; nt++) {
        float m0 = fmaxf(fmaxf(acc[0][nt][0], acc[0][nt][2]), fmaxf(acc[1][nt][0], acc[1][nt][2]));
        float m1 = fmaxf(fmaxf(acc[0][nt][1], acc[0][nt][3]), fmaxf(acc[1][nt][1], acc[1][nt][3]));
#pragma unroll
        for (int mk = 4; mk < 32; mk <<= 1) {
            m0 = fmaxf(m0, __shfl_xor_sync(0xffffffffu, m0, mk));
            m1 = fmaxf(m1, __shfl_xor_sync(0xffffffffu, m1, mk));
        }
        if (lid < 4) {
            atomicMax(&scol[wn * 128 + nt * 8 + 2 * lid],     fenc(m0));
            atomicMax(&scol[wn * 128 + nt * 8 + 2 * lid + 1], fenc(m1));
        }
    }
    __syncthreads();
    if (tid < 256) atomicMax(&g_scoreEnc[b * NP + p0 + tid], scol[tid]);
}

// ---------------- K2: hidden MLP ----------------
__global__ void k_hidden(const float* __restrict__ w1, const float* __restrict__ b1) {
    int j = blockIdx.x;
    int tid = threadIdx.x;
    const float* wr = w1 + (size_t)j * NIN;
    float acc[BB];
#pragma unroll
    for (int b = 0; b < BB; b++) acc[b] = 0.0f;
    for (int n = tid; n < NIN; n += 256) {
        float w = wr[n];
#pragma unroll
        for (int b = 0; b < BB; b++) acc[b] += w * g_mask[b * NIN + n];
    }
    __shared__ float red[BB][256];
#pragma unroll
    for (int b = 0; b < BB; b++) red[b][tid] = acc[b];
    __syncthreads();
    for (int s1 = 128; s1 > 0; s1 >>= 1) {
        if (tid < s1) {
#pragma unroll
            for (int b = 0; b < BB; b++) red[b][tid] += red[b][tid + s1];
        }
        __syncthreads();
    }
    if (tid < BB) g_h[tid * HID + j] = gelu_f(red[tid][0] + b1[j]);
}

// ---------------- K3a: relevance -> sigmoid (float4) ----------------
__global__ void k_relsig(const float* __restrict__ w2, const float* __restrict__ b2) {
    int warp = threadIdx.x >> 5, lane = threadIdx.x & 31;
    int p = blockIdx.x * 8 + warp;
    const float4* wr = (const float4*)(w2 + (size_t)p * HID);
    float acc[BB];
#pragma unroll
    for (int b = 0; b < BB; b++) acc[b] = 0.0f;
#pragma unroll 4
    for (int j = lane; j < HID / 4; j += 32) {
        float4 w = wr[j];
#pragma unroll
        for (int b = 0; b < BB; b++) {
            float4 h = ((const float4*)(g_h + b * HID))[j];
            acc[b] += w.x * h.x + w.y * h.y + w.z * h.z + w.w * h.w;
        }
    }
#pragma unroll
    for (int o = 16; o > 0; o >>= 1)
#pragma unroll
        for (int b = 0; b < BB; b++) acc[b] += __shfl_down_sync(0xffffffffu, acc[b], o);
    if (lane == 0) {
#pragma unroll
        for (int b = 0; b < BB; b++) {
            float rel = acc[b] + b2[p];
            g_sig[b * NP + p] = 1.0f / (1.0f + expf(-rel));
        }
    }
}

// ---------------- K4: approx top-NC (score inline) ----------------
__global__ void k_topkc() {
    __shared__ ull key[NP];
    int b = blockIdx.x, tid = threadIdx.x;
    for (int i = tid; i < NP; i += 1024) {
        float sc = gelu_f(fdec(g_scoreEnc[b * NP + i])) * g_sig[b * NP + i];
        key[i] = ((ull)fenc(sc) << 32) | (unsigned)i;
    }
    __syncthreads();
    for (int k = 2; k <= NP; k <<= 1) {
        for (int j = k >> 1; j > 0; j >>= 1) {
            for (int i = tid; i < NP; i += 1024) {
                int ix = i ^ j;
                if (ix > i) {
                    ull x = key[i], y = key[ix];
                    bool desc = ((i & k) == 0);
                    if (desc ? (x < y) : (x > y)) { key[i] = y; key[ix] = x; }
                }
            }
            __syncthreads();
        }
    }
    if (tid < NC) g_pidx512[b * NC + tid] = (int)(key[tid] & 0xffffffffu);
}

// ---------------- K5: refine — exact 3-pass z for NC cands ----------------
__global__ __launch_bounds__(256)
void k_refine() {
    extern __shared__ char smem[];
    const u32 sbase = smem_u32(smem);
    const int tid = threadIdx.x;
    const int wid = tid >> 5, lid = tid & 31;
    const int wm = wid & 3, wn = wid >> 2;
    const int b  = blockIdx.z;
    const int n0 = blockIdx.x * 128;
    const int s0 = blockIdx.y * 128;

    float acc[2][8][4];
#pragma unroll
    for (int i = 0; i < 2; i++)
#pragma unroll
        for (int j = 0; j < 8; j++)
#pragma unroll
            for (int r = 0; r < 4; r++) acc[i][j][r] = 0.0f;

    auto load_stage = [&](int ks, int buf) {
        const int k0 = ks * 32;
        u32 sg = sbase + buf * STGB4;
#pragma unroll
        for (int i = 0; i < 4; i++) {
            int idx = tid + i * 256;
            int sp = idx >> 9, rem = idx & 511;
            int r = rem >> 2, c = rem & 3;
            const __nv_bfloat16* g = g_Asp + ((size_t)(b * 2 + sp) * SS + s0 + r) * KIN + k0 + c * 8;
            cpasync16(sg + sp * PLANE + r * RPAD + c * 16, g);
        }
#pragma unroll
        for (int i = 0; i < 4; i++) {
            int idx = tid + i * 256;
            int sp = idx >> 9, rem = idx & 511;
            int r = rem >> 2, c = rem & 3;
            const __nv_bfloat16* g = g_Bc + ((size_t)(b * 2 + sp) * NC + n0 + r) * KIN + k0 + c * 8;
            cpasync16(sg + 2 * PLANE + sp * PLANE + r * RPAD + c * 16, g);
        }
    };

    const u32 aoff = (u32)((wm * 32 + (lid & 15)) * RPAD + (lid >> 4) * 16);
    const u32 boff = (u32)((wn * 64 + (lid & 15)) * RPAD + (lid >> 4) * 16);

    load_stage(0, 0); CP_COMMIT();

#pragma unroll 1
    for (int ks = 0; ks < KIN / 32; ks++) {
        int buf = ks & 1;
        if (ks < KIN / 32 - 1) { load_stage(ks + 1, buf ^ 1); CP_COMMIT(); CP_WAIT(1); }
        else                   { CP_WAIT(0); }
        __syncthreads();
        u32 sA = sbase + buf * STGB4;
        u32 sB = sA + 2 * PLANE;
#pragma unroll
        for (int kk = 0; kk < 2; kk++) {
            u32 ah[2][4], am[2][4];
#pragma unroll
            for (int mt = 0; mt < 2; mt++) {
                ldsm4(ah[mt], sA + aoff + mt * (16 * RPAD) + kk * 32);
                ldsm4(am[mt], sA + PLANE + aoff + mt * (16 * RPAD) + kk * 32);
            }
            u32 bh[4][4], bm[4][4];
#pragma unroll
            for (int nt2 = 0; nt2 < 4; nt2++) {
                ldsm4(bh[nt2], sB + boff + nt2 * (16 * RPAD) + kk * 32);
                ldsm4(bm[nt2], sB + PLANE + boff + nt2 * (16 * RPAD) + kk * 32);
            }
#pragma unroll
            for (int mt = 0; mt < 2; mt++)
#pragma unroll
                for (int nt2 = 0; nt2 < 4; nt2++) {
                    mma16816(acc[mt][2 * nt2],     ah[mt], bh[nt2][0], bh[nt2][2]);
                    mma16816(acc[mt][2 * nt2 + 1], ah[mt], bh[nt2][1], bh[nt2][3]);
                    mma16816(acc[mt][2 * nt2],     ah[mt], bm[nt2][0], bm[nt2][2]);
                    mma16816(acc[mt][2 * nt2 + 1], ah[mt], bm[nt2][1], bm[nt2][3]);
                    mma16816(acc[mt][2 * nt2],     am[mt], bh[nt2][0], bh[nt2][2]);
                    mma16816(acc[mt][2 * nt2 + 1], am[mt], bh[nt2][1], bh[nt2][3]);
                }
        }
        __syncthreads();
    }

    u32* scol = (u32*)smem;
    if (tid < 128) scol[tid] = 0u;
    __syncthreads();

    const size_t PL = (size_t)SS * NC;
#pragma unroll
    for (int mt = 0; mt < 2; mt++)
#pragma unroll
        for (int nt = 0; nt < 8; nt++) {
            int row = s0 + wm * 32 + mt * 16 + (lid >> 2);
            int col = n0 + wn * 64 + nt * 8 + 2 * (lid & 3);
            float g0 = gelu_f(acc[mt][nt][0]), g1 = gelu_f(acc[mt][nt][1]);
            float g2 = gelu_f(acc[mt][nt][2]), g3 = gelu_f(acc[mt][nt][3]);
            B2U h01, m01, h23, m23;
            split2(g0, h01.h[0], m01.h[0]); split2(g1, h01.h[1], m01.h[1]);
            split2(g2, h23.h[0], m23.h[0]); split2(g3, h23.h[1], m23.h[1]);
            size_t base = ((size_t)(b * 2) * SS + row) * NC + col;
            *(u32*)(g_PC + base)               = h01.u;
            *(u32*)(g_PC + base + PL)          = m01.u;
            *(u32*)(g_PC + base + 8 * NC)      = h23.u;
            *(u32*)(g_PC + base + PL + 8 * NC) = m23.u;
        }
#pragma unroll
    for (int nt = 0; nt < 8; nt++) {
        float m0 = fmaxf(fmaxf(acc[0][nt][0], acc[0][nt][2]), fmaxf(acc[1][nt][0], acc[1][nt][2]));
        float m1 = fmaxf(fmaxf(acc[0][nt][1], acc[0][nt][3]), fmaxf(acc[1][nt][1], acc[1][nt][3]));
#pragma unroll
        for (int mk = 4; mk < 32; mk <<= 1) {
            m0 = fmaxf(m0, __shfl_xor_sync(0xffffffffu, m0, mk));
            m1 = fmaxf(m1, __shfl_xor_sync(0xffffffffu, m1, mk));
        }
        if (lid < 4) {
            atomicMax(&scol[wn * 64 + nt * 8 + 2 * lid],     fenc(m0));
            atomicMax(&scol[wn * 64 + nt * 8 + 2 * lid + 1], fenc(m1));
        }
    }
    __syncthreads();
    if (tid < 128) atomicMax(&g_scoreEnc2[b * NC + n0 + tid], scol[tid]);
}

// ---------------- K6: exact rescore + top-256 (pad NC -> NCP) ----------------
__global__ void k_rescore() {
    __shared__ ull key[NCP];
    int b = blockIdx.x, tid = threadIdx.x;   // 512 threads
    if (tid < NC) {
        float z = fdec(g_scoreEnc2[b * NC + tid]);
        int p = g_pidx512[b * NC + tid];
        float sc = gelu_f(z) * g_sig[b * NP + p];
        key[tid] = ((ull)fenc(sc) << 32) | (unsigned)tid;
    } else {
        key[tid] = 0ULL;   // pad: sorts below all real (encoded) scores
    }
    __syncthreads();
    for (int k = 2; k <= NCP; k <<= 1) {
        for (int j = k >> 1; j > 0; j >>= 1) {
            int i = tid;
            int ix = i ^ j;
            if (ix > i) {
                ull x = key[i], y = key[ix];
                bool desc = ((i & k) == 0);
                if (desc ? (x < y) : (x > y)) { key[i] = y; key[ix] = x; }
            }
            __syncthreads();
        }
    }
    if (tid < KSEL) {
        int slot = (int)(key[tid] & 0xffffffffu);
        g_cmap[b * KSEL + tid] = slot;
        g_pidx[b * KSEL + tid] = g_pidx512[b * NC + slot];
    }
}

// ---------------- K7: compact via smem staging (coalesced) ----------------
__global__ void k_compact() {
    __shared__ __nv_bfloat16 st[2][8][NC];   // 12 KB
    __shared__ int cm[KSEL];
    int blk = blockIdx.x;                    // BB * SS/8 blocks
    int b = blk / (SS / 8);
    int s8 = (blk % (SS / 8)) * 8;
    int tid = threadIdx.x;
    if (tid < KSEL) cm[tid] = g_cmap[b * KSEL + tid];
    const int4* src0 = (const int4*)(g_PC + ((size_t)(b * 2)     * SS + s8) * NC);
    const int4* src1 = (const int4*)(g_PC + ((size_t)(b * 2 + 1) * SS + s8) * NC);
    int4* d0 = (int4*)&st[0][0][0];
    int4* d1 = (int4*)&st[1][0][0];
    const int NI4 = 8 * NC / 8;              // 8 rows * NC bf16 / 8 per int4 = 384
    for (int idx = tid; idx < NI4; idx += 256) {
        d0[idx] = src0[idx];
        d1[idx] = src1[idx];
    }
    __syncthreads();
    int j = tid;
    int c = cm[j];
    const size_t PLa = (size_t)SS * KSEL;
#pragma unroll
    for (int r = 0; r < 8; r++) {
        size_t dst = ((size_t)(b * 2) * SS + s8 + r) * KSEL + j;
        g_PA[dst]       = st[0][r][c];
        g_PA[dst + PLa] = st[1][r][c];
    }
}

// ---------------- K8: gather + transpose + split proj rows ----------------
__global__ void k_projsplit(const float* __restrict__ proj) {
    __shared__ float t[32][33];
    __shared__ int pj[32];
    int j0 = blockIdx.x * 32, d0 = blockIdx.y * 32, b = blockIdx.z;
    int tx = threadIdx.x, ty = threadIdx.y;
    if (ty == 0) pj[tx] = g_pidx[b * KSEL + j0 + tx];
    __syncthreads();
#pragma unroll
    for (int i = 0; i < 32; i += 8) {
        int p = pj[ty + i];
        t[ty + i][tx] = proj[(size_t)p * DM + d0 + tx];
    }
    __syncthreads();
    const size_t PL = (size_t)DM * KSEL;
#pragma unroll
    for (int i = 0; i < 32; i += 8) {
        float v = t[tx][ty + i];
        __nv_bfloat16 h, m;
        split2(v, h, m);
        size_t base = ((size_t)(b * 2) * DM + d0 + ty + i) * KSEL + j0 + tx;
        g_Pr[base]      = h;
        g_Pr[base + PL] = m;
    }
}

// ---------------- K9: final GEMM (HMMA 3-pass) ----------------
__global__ __launch_bounds__(256)
void k_gemm3t(float* __restrict__ out) {
    extern __shared__ char smem[];
    const u32 sbase = smem_u32(smem);
    const int tid = threadIdx.x;
    const int wid = tid >> 5, lid = tid & 31;
    const int wm = wid & 3, wn = wid >> 2;
    const int b  = blockIdx.z;
    const int d0 = blockIdx.x * 128;
    const int s0 = blockIdx.y * 128;

    float acc[2][8][4];
#pragma unroll
    for (int i = 0; i < 2; i++)
#pragma unroll
        for (int j = 0; j < 8; j++)
#pragma unroll
            for (int r = 0; r < 4; r++) acc[i][j][r] = 0.0f;

    auto load_stage = [&](int ks, int buf) {
        const int k0 = ks * 32;
        u32 sg = sbase + buf * STGB4;
#pragma unroll
        for (int i = 0; i < 4; i++) {
            int idx = tid + i * 256;
            int sp = idx >> 9, rem = idx & 511;
            int r = rem >> 2, c = rem & 3;
            const __nv_bfloat16* g = g_PA + ((size_t)(b * 2 + sp) * SS + s0 + r) * KSEL + k0 + c * 8;
            cpasync16(sg + sp * PLANE + r * RPAD + c * 16, g);
        }
#pragma unroll
        for (int i = 0; i < 4; i++) {
            int idx = tid + i * 256;
            int sp = idx >> 9, rem = idx & 511;
            int r = rem >> 2, c = rem & 3;
            const __nv_bfloat16* g = g_Pr + ((size_t)(b * 2 + sp) * DM + d0 + r) * KSEL + k0 + c * 8;
            cpasync16(sg + 2 * PLANE + sp * PLANE + r * RPAD + c * 16, g);
        }
    };

    const u32 aoff = (u32)((wm * 32 + (lid & 15)) * RPAD + (lid >> 4) * 16);
    const u32 boff = (u32)((wn * 64 + (lid & 15)) * RPAD + (lid >> 4) * 16);

    load_stage(0, 0); CP_COMMIT();

#pragma unroll 1
    for (int ks = 0; ks < KSEL / 32; ks++) {
        int buf = ks & 1;
        if (ks < KSEL / 32 - 1) { load_stage(ks + 1, buf ^ 1); CP_COMMIT(); CP_WAIT(1); }
        else                    { CP_WAIT(0); }
        __syncthreads();
        u32 sA = sbase + buf * STGB4;
        u32 sB = sA + 2 * PLANE;
#pragma unroll
        for (int kk = 0; kk < 2; kk++) {
            u32 ah[2][4], am[2][4];
#pragma unroll
            for (int mt = 0; mt < 2; mt++) {
                ldsm4(ah[mt], sA + aoff + mt * (16 * RPAD) + kk * 32);
                ldsm4(am[mt], sA + PLANE + aoff + mt * (16 * RPAD) + kk * 32);
            }
            u32 bh[4][4], bm[4][4];
#pragma unroll
            for (int nt2 = 0; nt2 < 4; nt2++) {
                ldsm4(bh[nt2], sB + boff + nt2 * (16 * RPAD) + kk * 32);
                ldsm4(bm[nt2], sB + PLANE + boff + nt2 * (16 * RPAD) + kk * 32);
            }
#pragma unroll
            for (int mt = 0; mt < 2; mt++)
#pragma unroll
                for (int nt2 = 0; nt2 < 4; nt2++) {
                    mma16816(acc[mt][2 * nt2],     ah[mt], bh[nt2][0], bh[nt2][2]);
                    mma16816(acc[mt][2 * nt2 + 1], ah[mt], bh[nt2][1], bh[nt2][3]);
                    mma16816(acc[mt][2 * nt2],     ah[mt], bm[nt2][0], bm[nt2][2]);
                    mma16816(acc[mt][2 * nt2 + 1], ah[mt], bm[nt2][1], bm[nt2][3]);
                    mma16816(acc[mt][2 * nt2],     am[mt], bh[nt2][0], bh[nt2][2]);
                    mma16816(acc[mt][2 * nt2 + 1], am[mt], bh[nt2][1], bh[nt2][3]);
                }
        }
        __syncthreads();
    }
#pragma unroll
    for (int mt = 0; mt < 2; mt++)
#pragma unroll
        for (int nt = 0; nt < 8; nt++) {
            int row = s0 + wm * 32 + mt * 16 + (lid >> 2);
            int col = d0 + wn * 64 + nt * 8 + 2 * (lid & 3);
            float* po = out + ((size_t)b * SS + row) * DM + col;
            *(float2*)po            = make_float2(acc[mt][nt][0], acc[mt][nt][1]);
            *(float2*)(po + 8 * DM) = make_float2(acc[mt][nt][2], acc[mt][nt][3]);
        }
}

// ---------------- entry (multi-stream fork/join) ----------------
extern "C" void kernel_launch(void* const* d_in, const int* in_sizes, int n_in,
                              void* d_out, int out_size) {
    const float* act  = (const float*)d_in[0];
    const int*   sidx = (const int*)d_in[1];
    int o = (n_in >= 9 && in_sizes[2] == 1) ? 3 : 2;
    const float* cw   = (const float*)d_in[o + 0];
    const float* proj = (const float*)d_in[o + 1];
    const float* w1   = (const float*)d_in[o + 2];
    const float* b1   = (const float*)d_in[o + 3];
    const float* w2   = (const float*)d_in[o + 4];
    const float* b2   = (const float*)d_in[o + 5];
    float* out = (float*)d_out;

    static cudaStream_t s1 = nullptr;
    static cudaEvent_t ev0 = nullptr, ev1 = nullptr, ev2 = nullptr, ev3 = nullptr;
    if (s1 == nullptr) {
        cudaStreamCreateWithFlags(&s1, cudaStreamNonBlocking);
        cudaEventCreateWithFlags(&ev0, cudaEventDisableTiming);
        cudaEventCreateWithFlags(&ev1, cudaEventDisableTiming);
        cudaEventCreateWithFlags(&ev2, cudaEventDisableTiming);
        cudaEventCreateWithFlags(&ev3, cudaEventDisableTiming);
        cudaFuncSetAttribute(k_gemm1a, cudaFuncAttributeMaxDynamicSharedMemorySize, GSMEM1);
        cudaFuncSetAttribute(k_refine, cudaFuncAttributeMaxDynamicSharedMemorySize, GSMEM4);
        cudaFuncSetAttribute(k_gemm3t, cudaFuncAttributeMaxDynamicSharedMemorySize, GSMEM4);
    }

    // fork: A m-plane split + MLP chain on s1
    cudaEventRecord(ev0, 0);
    cudaStreamWaitEvent(s1, ev0, 0);
    k_splitAm<<<(BB * SS * KIN / 4) / 256, 256, 0, s1>>>(act);
    k_initMask<<<(BB * NIN + 255) / 256, 256, 0, s1>>>();
    k_scatter<<<(BB * KIN + 255) / 256, 256, 0, s1>>>(sidx);
    k_hidden<<<HID, 256, 0, s1>>>(w1, b1);
    k_relsig<<<NP / 8, 256, 0, s1>>>(w2, b2);
    cudaEventRecord(ev1, s1);

    // main chain
    k_initScore<<<(BB * NP + 255) / 256, 256>>>();
    k_splitAh<<<(BB * SS * KIN / 4) / 256, 256>>>(act);
    k_gatherBh<<<NP, 256>>>(cw, sidx);
    k_gemm1a<<<dim3(NP / 256, SS / 128, BB), 256, GSMEM1>>>();

    // join
    cudaStreamWaitEvent(0, ev1, 0);
    k_topkc<<<BB, 1024>>>();
    k_gatherBc<<<BB * NC, 256>>>(cw, sidx);
    k_refine<<<dim3(NC / 128, SS / 128, BB), 256, GSMEM4>>>();
    k_rescore<<<BB, NCP>>>();

    // fork: projsplit on s1, compact on main
    cudaEventRecord(ev2, 0);
    cudaStreamWaitEvent(s1, ev2, 0);
    k_projsplit<<<dim3(KSEL / 32, DM / 32, BB), dim3(32, 8), 0, s1>>>(proj);
    cudaEventRecord(ev3, s1);
    k_compact<<<BB * SS / 8, 256>>>();
    cudaStreamWaitEvent(0, ev3, 0);

    k_gemm3t<<<dim3(DM / 128, SS / 128, BB), 256, GSMEM4>>>(out);
}

// round 9
// speedup vs baseline: 1.6438x; 1.0583x over previous
#include <cuda_runtime.h>
#include <cuda_bf16.h>

#define BB   8
#define SS   2048
#define KIN  512
#define NIN  2048
#define NP   4096
#define HID  4096
#define DM   1024
#define KSEL 256
#define NC   384     // refine candidate count
#define NCP  512     // padded for bitonic

typedef unsigned long long ull;
typedef unsigned int u32;

// ---------------- scratch ----------------
__device__ __align__(256) __nv_bfloat16 g_Asp[(size_t)BB * 2 * SS * KIN];
__device__ __align__(256) __nv_bfloat16 g_Bh [(size_t)BB * NP * KIN];
__device__ __align__(256) __nv_bfloat16 g_Bc [(size_t)BB * 2 * NC * KIN];
__device__ __align__(256) __nv_bfloat16 g_PC [(size_t)BB * 2 * SS * NC];
__device__ __align__(256) __nv_bfloat16 g_PA [(size_t)BB * 2 * SS * KSEL];
__device__ __align__(256) __nv_bfloat16 g_Pr [(size_t)BB * 2 * DM * KSEL];
__device__ float    g_mask[BB * NIN];
__device__ float    g_h[BB * HID];
__device__ float    g_sig[BB * NP];
__device__ unsigned g_scoreEnc[BB * NP];
__device__ unsigned g_scoreEnc2[BB * NC];
__device__ int      g_pidx512[BB * NC];
__device__ int      g_pidx[BB * KSEL];
__device__ int      g_cmap[BB * KSEL];

// ---------------- helpers ----------------
__device__ __forceinline__ unsigned fenc(float f) {
    unsigned u = __float_as_uint(f);
    return (u & 0x80000000u) ? ~u : (u | 0x80000000u);
}
__device__ __forceinline__ float fdec(unsigned u) {
    return __uint_as_float((u & 0x80000000u) ? (u & 0x7fffffffu) : ~u);
}
__device__ __forceinline__ float gelu_f(float x) {
    return 0.5f * x * (1.0f + erff(x * 0.70710678118654752f));
}
__device__ __forceinline__ u32 smem_u32(const void* p) {
    u32 a; asm("{ .reg .u64 t; cvta.to.shared.u64 t, %1; cvt.u32.u64 %0, t; }" : "=r"(a) : "l"(p));
    return a;
}
__device__ __forceinline__ void split2(float a, __nv_bfloat16& h, __nv_bfloat16& m) {
    h = __float2bfloat16(a);
    m = __float2bfloat16(a - __bfloat162float(h));
}

// ---------------- mma.sync / ldmatrix / cp.async ----------------
__device__ __forceinline__ void mma16816(float* d, const u32* a, u32 b0, u32 b1) {
    asm volatile("mma.sync.aligned.m16n8k16.row.col.f32.bf16.bf16.f32 "
        "{%0,%1,%2,%3}, {%4,%5,%6,%7}, {%8,%9}, {%0,%1,%2,%3};"
        : "+f"(d[0]), "+f"(d[1]), "+f"(d[2]), "+f"(d[3])
        : "r"(a[0]), "r"(a[1]), "r"(a[2]), "r"(a[3]), "r"(b0), "r"(b1));
}
__device__ __forceinline__ void ldsm4(u32* r, u32 addr) {
    asm volatile("ldmatrix.sync.aligned.m8n8.x4.shared.b16 {%0,%1,%2,%3}, [%4];"
        : "=r"(r[0]), "=r"(r[1]), "=r"(r[2]), "=r"(r[3]) : "r"(addr));
}
__device__ __forceinline__ void cpasync16(u32 dst, const void* src) {
    asm volatile("cp.async.cg.shared.global [%0], [%1], 16;" :: "r"(dst), "l"(src));
}
#define CP_COMMIT() asm volatile("cp.async.commit_group;" ::: "memory")
#define CP_WAIT(n)  asm volatile("cp.async.wait_group %0;" :: "n"(n) : "memory")

#define RPAD   80
#define PLANE  (128 * RPAD)          // 10240
#define STGB4  (4 * PLANE)           // refine/gemm3t stage: 40960
#define GSMEM4 (2 * STGB4)           // 81920 -> 2 CTAs/SM
#define STG1   (2 * PLANE)           // gemm1a stage (A-h + B-h): 20480
#define GSMEM1 (2 * STG1)            // 40960 -> 2 CTAs/SM (reg-limited)

// ---------------- init kernels ----------------
__global__ void k_initMask() {
    int t = blockIdx.x * blockDim.x + threadIdx.x;
    if (t < BB * NIN) g_mask[t] = 0.0f;
}
__global__ void k_initScore() {
    int t = blockIdx.x * blockDim.x + threadIdx.x;
    if (t < BB * NP)  g_scoreEnc[t] = 0u;
    if (t < BB * NC)  g_scoreEnc2[t] = 0u;
}
__global__ void k_scatter(const int* __restrict__ sidx) {
    int t = blockIdx.x * blockDim.x + threadIdx.x;
    if (t < BB * KIN) {
        int b = t >> 9;
        g_mask[b * NIN + sidx[t]] = 1.0f;
    }
}

// ---------------- split A planes ----------------
union B4U { __nv_bfloat16 h[4]; ull u; };
union B2U { __nv_bfloat16 h[2]; u32 u; };

__global__ void k_splitAh(const float* __restrict__ act) {
    size_t t = (size_t)blockIdx.x * 256 + threadIdx.x;
    size_t bs = t >> 7;
    int k4 = (int)(t & 127);
    int b = (int)(bs >> 11), s = (int)(bs & 2047);
    float4 v = ((const float4*)act)[t];
    float vv[4] = { v.x, v.y, v.z, v.w };
    B4U hh;
#pragma unroll
    for (int i = 0; i < 4; i++) hh.h[i] = __float2bfloat16(vv[i]);
    *(ull*)(g_Asp + ((size_t)(b * 2) * SS + s) * KIN + k4 * 4) = hh.u;
}

__global__ void k_splitAm(const float* __restrict__ act) {
    size_t t = (size_t)blockIdx.x * 256 + threadIdx.x;
    size_t bs = t >> 7;
    int k4 = (int)(t & 127);
    int b = (int)(bs >> 11), s = (int)(bs & 2047);
    float4 v = ((const float4*)act)[t];
    float vv[4] = { v.x, v.y, v.z, v.w };
    B4U mm;
#pragma unroll
    for (int i = 0; i < 4; i++) {
        __nv_bfloat16 h = __float2bfloat16(vv[i]);
        mm.h[i] = __float2bfloat16(vv[i] - __bfloat162float(h));
    }
    *(ull*)(g_Asp + ((size_t)(b * 2 + 1) * SS + s) * KIN + k4 * 4) = mm.u;
}

// ---------------- gather B h-plane (full 4096 rows) ----------------
__global__ void k_gatherBh(const float* __restrict__ cw, const int* __restrict__ sidx) {
    __shared__ float row[NIN];
    __shared__ int sidxS[BB * KIN];    // 16 KB
    int p = blockIdx.x, tid = threadIdx.x;
    for (int i = tid; i < NIN; i += 256) row[i] = cw[(size_t)p * NIN + i];
    for (int i = tid; i < BB * KIN / 4; i += 256)
        ((int4*)sidxS)[i] = ((const int4*)sidx)[i];
    __syncthreads();
    int k = tid * 2;
#pragma unroll 1
    for (int b = 0; b < BB; b++) {
        int i0 = sidxS[b * KIN + k], i1 = sidxS[b * KIN + k + 1];
        B2U hh;
        hh.h[0] = __float2bfloat16(row[i0]);
        hh.h[1] = __float2bfloat16(row[i1]);
        *(u32*)(g_Bh + ((size_t)b * NP + p) * KIN + k) = hh.u;
    }
}

// ---------------- gather B splits for NC candidates ----------------
__global__ void k_gatherBc(const float* __restrict__ cw, const int* __restrict__ sidx) {
    __shared__ float row[NIN];
    int blk = blockIdx.x;              // b * NC + j
    int b = blk / NC, j = blk % NC;
    int tid = threadIdx.x;
    int p = g_pidx512[b * NC + j];
    for (int i = tid; i < NIN; i += 256) row[i] = cw[(size_t)p * NIN + i];
    __syncthreads();
    int k = tid * 2;
    int i0 = sidx[b * KIN + k], i1 = sidx[b * KIN + k + 1];
    B2U hh, mm;
    split2(row[i0], hh.h[0], mm.h[0]);
    split2(row[i1], hh.h[1], mm.h[1]);
    const size_t PL = (size_t)NC * KIN;
    size_t base = ((size_t)(b * 2) * NC + j) * KIN + k;
    *(u32*)(g_Bc + base)      = hh.u;
    *(u32*)(g_Bc + base + PL) = mm.u;
}

// ---------------- K1a: approx score GEMM, 128x128 tile, 2 CTAs/SM ----------------
__global__ __launch_bounds__(256, 2)
void k_gemm1a() {
    extern __shared__ char smem[];
    const u32 sbase = smem_u32(smem);
    const int tid = threadIdx.x;
    const int wid = tid >> 5, lid = tid & 31;
    const int wm = wid & 3, wn = wid >> 2;       // warp tile 32 x 64
    const int b  = blockIdx.z;
    const int p0 = blockIdx.x * 128;
    const int s0 = blockIdx.y * 128;

    float acc[2][8][4];
#pragma unroll
    for (int i = 0; i < 2; i++)
#pragma unroll
        for (int j = 0; j < 8; j++)
#pragma unroll
            for (int r = 0; r < 4; r++) acc[i][j][r] = 0.0f;

    auto load_stage = [&](int ks, int buf) {
        const int k0 = ks * 32;
        u32 sgA = sbase + buf * STG1;
        u32 sgB = sgA + PLANE;
#pragma unroll
        for (int i = 0; i < 2; i++) {      // A h-plane: 512 chunks
            int idx = tid + i * 256;
            int r = idx >> 2, c = idx & 3;
            const __nv_bfloat16* g = g_Asp + ((size_t)(b * 2) * SS + s0 + r) * KIN + k0 + c * 8;
            cpasync16(sgA + r * RPAD + c * 16, g);
        }
#pragma unroll
        for (int i = 0; i < 2; i++) {      // B h-plane: 512 chunks
            int idx = tid + i * 256;
            int r = idx >> 2, c = idx & 3;
            const __nv_bfloat16* g = g_Bh + ((size_t)b * NP + p0 + r) * KIN + k0 + c * 8;
            cpasync16(sgB + r * RPAD + c * 16, g);
        }
    };

    const u32 aoff = (u32)((wm * 32 + (lid & 15)) * RPAD + (lid >> 4) * 16);
    const u32 boff = (u32)((wn * 64 + (lid & 15)) * RPAD + (lid >> 4) * 16);

    load_stage(0, 0); CP_COMMIT();

#pragma unroll 1
    for (int ks = 0; ks < KIN / 32; ks++) {
        int buf = ks & 1;
        if (ks < KIN / 32 - 1) { load_stage(ks + 1, buf ^ 1); CP_COMMIT(); CP_WAIT(1); }
        else                   { CP_WAIT(0); }
        __syncthreads();
        u32 sA = sbase + buf * STG1;
        u32 sB = sA + PLANE;
#pragma unroll
        for (int kk = 0; kk < 2; kk++) {
            u32 ah[2][4];
#pragma unroll
            for (int mt = 0; mt < 2; mt++)
                ldsm4(ah[mt], sA + aoff + mt * (16 * RPAD) + kk * 32);
            u32 bh[4][4];
#pragma unroll
            for (int q = 0; q < 4; q++)
                ldsm4(bh[q], sB + boff + q * (16 * RPAD) + kk * 32);
#pragma unroll
            for (int mt = 0; mt < 2; mt++)
#pragma unroll
                for (int q = 0; q < 4; q++) {
                    mma16816(acc[mt][2 * q],     ah[mt], bh[q][0], bh[q][2]);
                    mma16816(acc[mt][2 * q + 1], ah[mt], bh[q][1], bh[q][3]);
                }
        }
        __syncthreads();
    }

    u32* scol = (u32*)smem;
    if (tid < 128) scol[tid] = 0u;
    __syncthreads();
#pragma unroll
    for (int nt = 0; nt < 8; nt++) {
        float m0 = fmaxf(fmaxf(acc[0][nt][0], acc[0][nt][2]), fmaxf(acc[1][nt][0], acc[1][nt][2]));
        float m1 = fmaxf(fmaxf(acc[0][nt][1], acc[0][nt][3]), fmaxf(acc[1][nt][1], acc[1][nt][3]));
#pragma unroll
        for (int mk = 4; mk < 32; mk <<= 1) {
            m0 = fmaxf(m0, __shfl_xor_sync(0xffffffffu, m0, mk));
            m1 = fmaxf(m1, __shfl_xor_sync(0xffffffffu, m1, mk));
        }
        if (lid < 4) {
            atomicMax(&scol[wn * 64 + nt * 8 + 2 * lid],     fenc(m0));
            atomicMax(&scol[wn * 64 + nt * 8 + 2 * lid + 1], fenc(m1));
        }
    }
    __syncthreads();
    if (tid < 128) atomicMax(&g_scoreEnc[b * NP + p0 + tid], scol[tid]);
}

// ---------------- K2: hidden MLP ----------------
__global__ void k_hidden(const float* __restrict__ w1, const float* __restrict__ b1) {
    int j = blockIdx.x;
    int tid = threadIdx.x;
    const float* wr = w1 + (size_t)j * NIN;
    float acc[BB];
#pragma unroll
    for (int b = 0; b < BB; b++) acc[b] = 0.0f;
    for (int n = tid; n < NIN; n += 256) {
        float w = wr[n];
#pragma unroll
        for (int b = 0; b < BB; b++) acc[b] += w * g_mask[b * NIN + n];
    }
    __shared__ float red[BB][256];
#pragma unroll
    for (int b = 0; b < BB; b++) red[b][tid] = acc[b];
    __syncthreads();
    for (int s1 = 128; s1 > 0; s1 >>= 1) {
        if (tid < s1) {
#pragma unroll
            for (int b = 0; b < BB; b++) red[b][tid] += red[b][tid + s1];
        }
        __syncthreads();
    }
    if (tid < BB) g_h[tid * HID + j] = gelu_f(red[tid][0] + b1[j]);
}

// ---------------- K3a: relevance -> sigmoid (float4) ----------------
__global__ void k_relsig(const float* __restrict__ w2, const float* __restrict__ b2) {
    int warp = threadIdx.x >> 5, lane = threadIdx.x & 31;
    int p = blockIdx.x * 8 + warp;
    const float4* wr = (const float4*)(w2 + (size_t)p * HID);
    float acc[BB];
#pragma unroll
    for (int b = 0; b < BB; b++) acc[b] = 0.0f;
#pragma unroll 4
    for (int j = lane; j < HID / 4; j += 32) {
        float4 w = wr[j];
#pragma unroll
        for (int b = 0; b < BB; b++) {
            float4 h = ((const float4*)(g_h + b * HID))[j];
            acc[b] += w.x * h.x + w.y * h.y + w.z * h.z + w.w * h.w;
        }
    }
#pragma unroll
    for (int o = 16; o > 0; o >>= 1)
#pragma unroll
        for (int b = 0; b < BB; b++) acc[b] += __shfl_down_sync(0xffffffffu, acc[b], o);
    if (lane == 0) {
#pragma unroll
        for (int b = 0; b < BB; b++) {
            float rel = acc[b] + b2[p];
            g_sig[b * NP + p] = 1.0f / (1.0f + expf(-rel));
        }
    }
}

// ---------------- K4: approx top-NC (score inline) ----------------
__global__ void k_topkc() {
    __shared__ ull key[NP];
    int b = blockIdx.x, tid = threadIdx.x;
    for (int i = tid; i < NP; i += 1024) {
        float sc = gelu_f(fdec(g_scoreEnc[b * NP + i])) * g_sig[b * NP + i];
        key[i] = ((ull)fenc(sc) << 32) | (unsigned)i;
    }
    __syncthreads();
    for (int k = 2; k <= NP; k <<= 1) {
        for (int j = k >> 1; j > 0; j >>= 1) {
            for (int i = tid; i < NP; i += 1024) {
                int ix = i ^ j;
                if (ix > i) {
                    ull x = key[i], y = key[ix];
                    bool desc = ((i & k) == 0);
                    if (desc ? (x < y) : (x > y)) { key[i] = y; key[ix] = x; }
                }
            }
            __syncthreads();
        }
    }
    if (tid < NC) g_pidx512[b * NC + tid] = (int)(key[tid] & 0xffffffffu);
}

// ---------------- K5: refine — exact 3-pass z for NC cands ----------------
__global__ __launch_bounds__(256)
void k_refine() {
    extern __shared__ char smem[];
    const u32 sbase = smem_u32(smem);
    const int tid = threadIdx.x;
    const int wid = tid >> 5, lid = tid & 31;
    const int wm = wid & 3, wn = wid >> 2;
    const int b  = blockIdx.z;
    const int n0 = blockIdx.x * 128;
    const int s0 = blockIdx.y * 128;

    float acc[2][8][4];
#pragma unroll
    for (int i = 0; i < 2; i++)
#pragma unroll
        for (int j = 0; j < 8; j++)
#pragma unroll
            for (int r = 0; r < 4; r++) acc[i][j][r] = 0.0f;

    auto load_stage = [&](int ks, int buf) {
        const int k0 = ks * 32;
        u32 sg = sbase + buf * STGB4;
#pragma unroll
        for (int i = 0; i < 4; i++) {
            int idx = tid + i * 256;
            int sp = idx >> 9, rem = idx & 511;
            int r = rem >> 2, c = rem & 3;
            const __nv_bfloat16* g = g_Asp + ((size_t)(b * 2 + sp) * SS + s0 + r) * KIN + k0 + c * 8;
            cpasync16(sg + sp * PLANE + r * RPAD + c * 16, g);
        }
#pragma unroll
        for (int i = 0; i < 4; i++) {
            int idx = tid + i * 256;
            int sp = idx >> 9, rem = idx & 511;
            int r = rem >> 2, c = rem & 3;
            const __nv_bfloat16* g = g_Bc + ((size_t)(b * 2 + sp) * NC + n0 + r) * KIN + k0 + c * 8;
            cpasync16(sg + 2 * PLANE + sp * PLANE + r * RPAD + c * 16, g);
        }
    };

    const u32 aoff = (u32)((wm * 32 + (lid & 15)) * RPAD + (lid >> 4) * 16);
    const u32 boff = (u32)((wn * 64 + (lid & 15)) * RPAD + (lid >> 4) * 16);

    load_stage(0, 0); CP_COMMIT();

#pragma unroll 1
    for (int ks = 0; ks < KIN / 32; ks++) {
        int buf = ks & 1;
        if (ks < KIN / 32 - 1) { load_stage(ks + 1, buf ^ 1); CP_COMMIT(); CP_WAIT(1); }
        else                   { CP_WAIT(0); }
        __syncthreads();
        u32 sA = sbase + buf * STGB4;
        u32 sB = sA + 2 * PLANE;
#pragma unroll
        for (int kk = 0; kk < 2; kk++) {
            u32 ah[2][4], am[2][4];
#pragma unroll
            for (int mt = 0; mt < 2; mt++) {
                ldsm4(ah[mt], sA + aoff + mt * (16 * RPAD) + kk * 32);
                ldsm4(am[mt], sA + PLANE + aoff + mt * (16 * RPAD) + kk * 32);
            }
            u32 bh[4][4], bm[4][4];
#pragma unroll
            for (int nt2 = 0; nt2 < 4; nt2++) {
                ldsm4(bh[nt2], sB + boff + nt2 * (16 * RPAD) + kk * 32);
                ldsm4(bm[nt2], sB + PLANE + boff + nt2 * (16 * RPAD) + kk * 32);
            }
#pragma unroll
            for (int mt = 0; mt < 2; mt++)
#pragma unroll
                for (int nt2 = 0; nt2 < 4; nt2++) {
                    mma16816(acc[mt][2 * nt2],     ah[mt], bh[nt2][0], bh[nt2][2]);
                    mma16816(acc[mt][2 * nt2 + 1], ah[mt], bh[nt2][1], bh[nt2][3]);
                    mma16816(acc[mt][2 * nt2],     ah[mt], bm[nt2][0], bm[nt2][2]);
                    mma16816(acc[mt][2 * nt2 + 1], ah[mt], bm[nt2][1], bm[nt2][3]);
                    mma16816(acc[mt][2 * nt2],     am[mt], bh[nt2][0], bh[nt2][2]);
                    mma16816(acc[mt][2 * nt2 + 1], am[mt], bh[nt2][1], bh[nt2][3]);
                }
        }
        __syncthreads();
    }

    u32* scol = (u32*)smem;
    if (tid < 128) scol[tid] = 0u;
    __syncthreads();

    const size_t PL = (size_t)SS * NC;
#pragma unroll
    for (int mt = 0; mt < 2; mt++)
#pragma unroll
        for (int nt = 0; nt < 8; nt++) {
            int row = s0 + wm * 32 + mt * 16 + (lid >> 2);
            int col = n0 + wn * 64 + nt * 8 + 2 * (lid & 3);
            float g0 = gelu_f(acc[mt][nt][0]), g1 = gelu_f(acc[mt][nt][1]);
            float g2 = gelu_f(acc[mt][nt][2]), g3 = gelu_f(acc[mt][nt][3]);
            B2U h01, m01, h23, m23;
            split2(g0, h01.h[0], m01.h[0]); split2(g1, h01.h[1], m01.h[1]);
            split2(g2, h23.h[0], m23.h[0]); split2(g3, h23.h[1], m23.h[1]);
            size_t base = ((size_t)(b * 2) * SS + row) * NC + col;
            *(u32*)(g_PC + base)               = h01.u;
            *(u32*)(g_PC + base + PL)          = m01.u;
            *(u32*)(g_PC + base + 8 * NC)      = h23.u;
            *(u32*)(g_PC + base + PL + 8 * NC) = m23.u;
        }
#pragma unroll
    for (int nt = 0; nt < 8; nt++) {
        float m0 = fmaxf(fmaxf(acc[0][nt][0], acc[0][nt][2]), fmaxf(acc[1][nt][0], acc[1][nt][2]));
        float m1 = fmaxf(fmaxf(acc[0][nt][1], acc[0][nt][3]), fmaxf(acc[1][nt][1], acc[1][nt][3]));
#pragma unroll
        for (int mk = 4; mk < 32; mk <<= 1) {
            m0 = fmaxf(m0, __shfl_xor_sync(0xffffffffu, m0, mk));
            m1 = fmaxf(m1, __shfl_xor_sync(0xffffffffu, m1, mk));
        }
        if (lid < 4) {
            atomicMax(&scol[wn * 64 + nt * 8 + 2 * lid],     fenc(m0));
            atomicMax(&scol[wn * 64 + nt * 8 + 2 * lid + 1], fenc(m1));
        }
    }
    __syncthreads();
    if (tid < 128) atomicMax(&g_scoreEnc2[b * NC + n0 + tid], scol[tid]);
}

// ---------------- K6: exact rescore + top-256 (pad NC -> NCP) ----------------
__global__ void k_rescore() {
    __shared__ ull key[NCP];
    int b = blockIdx.x, tid = threadIdx.x;   // 512 threads
    if (tid < NC) {
        float z = fdec(g_scoreEnc2[b * NC + tid]);
        int p = g_pidx512[b * NC + tid];
        float sc = gelu_f(z) * g_sig[b * NP + p];
        key[tid] = ((ull)fenc(sc) << 32) | (unsigned)tid;
    } else {
        key[tid] = 0ULL;
    }
    __syncthreads();
    for (int k = 2; k <= NCP; k <<= 1) {
        for (int j = k >> 1; j > 0; j >>= 1) {
            int i = tid;
            int ix = i ^ j;
            if (ix > i) {
                ull x = key[i], y = key[ix];
                bool desc = ((i & k) == 0);
                if (desc ? (x < y) : (x > y)) { key[i] = y; key[ix] = x; }
            }
            __syncthreads();
        }
    }
    if (tid < KSEL) {
        int slot = (int)(key[tid] & 0xffffffffu);
        g_cmap[b * KSEL + tid] = slot;
        g_pidx[b * KSEL + tid] = g_pidx512[b * NC + slot];
    }
}

// ---------------- K7: compact via smem staging (coalesced) ----------------
__global__ void k_compact() {
    __shared__ __nv_bfloat16 st[2][8][NC];   // 12 KB
    __shared__ int cm[KSEL];
    int blk = blockIdx.x;                    // BB * SS/8 blocks
    int b = blk / (SS / 8);
    int s8 = (blk % (SS / 8)) * 8;
    int tid = threadIdx.x;
    if (tid < KSEL) cm[tid] = g_cmap[b * KSEL + tid];
    const int4* src0 = (const int4*)(g_PC + ((size_t)(b * 2)     * SS + s8) * NC);
    const int4* src1 = (const int4*)(g_PC + ((size_t)(b * 2 + 1) * SS + s8) * NC);
    int4* d0 = (int4*)&st[0][0][0];
    int4* d1 = (int4*)&st[1][0][0];
    const int NI4 = 8 * NC / 8;
    for (int idx = tid; idx < NI4; idx += 256) {
        d0[idx] = src0[idx];
        d1[idx] = src1[idx];
    }
    __syncthreads();
    int j = tid;
    int c = cm[j];
    const size_t PLa = (size_t)SS * KSEL;
#pragma unroll
    for (int r = 0; r < 8; r++) {
        size_t dst = ((size_t)(b * 2) * SS + s8 + r) * KSEL + j;
        g_PA[dst]       = st[0][r][c];
        g_PA[dst + PLa] = st[1][r][c];
    }
}

// ---------------- K8: gather + transpose + split proj rows ----------------
__global__ void k_projsplit(const float* __restrict__ proj) {
    __shared__ float t[32][33];
    __shared__ int pj[32];
    int j0 = blockIdx.x * 32, d0 = blockIdx.y * 32, b = blockIdx.z;
    int tx = threadIdx.x, ty = threadIdx.y;
    if (ty == 0) pj[tx] = g_pidx[b * KSEL + j0 + tx];
    __syncthreads();
#pragma unroll
    for (int i = 0; i < 32; i += 8) {
        int p = pj[ty + i];
        t[ty + i][tx] = proj[(size_t)p * DM + d0 + tx];
    }
    __syncthreads();
    const size_t PL = (size_t)DM * KSEL;
#pragma unroll
    for (int i = 0; i < 32; i += 8) {
        float v = t[tx][ty + i];
        __nv_bfloat16 h, m;
        split2(v, h, m);
        size_t base = ((size_t)(b * 2) * DM + d0 + ty + i) * KSEL + j0 + tx;
        g_Pr[base]      = h;
        g_Pr[base + PL] = m;
    }
}

// ---------------- K9: final GEMM (HMMA 3-pass) ----------------
__global__ __launch_bounds__(256)
void k_gemm3t(float* __restrict__ out) {
    extern __shared__ char smem[];
    const u32 sbase = smem_u32(smem);
    const int tid = threadIdx.x;
    const int wid = tid >> 5, lid = tid & 31;
    const int wm = wid & 3, wn = wid >> 2;
    const int b  = blockIdx.z;
    const int d0 = blockIdx.x * 128;
    const int s0 = blockIdx.y * 128;

    float acc[2][8][4];
#pragma unroll
    for (int i = 0; i < 2; i++)
#pragma unroll
        for (int j = 0; j < 8; j++)
#pragma unroll
            for (int r = 0; r < 4; r++) acc[i][j][r] = 0.0f;

    auto load_stage = [&](int ks, int buf) {
        const int k0 = ks * 32;
        u32 sg = sbase + buf * STGB4;
#pragma unroll
        for (int i = 0; i < 4; i++) {
            int idx = tid + i * 256;
            int sp = idx >> 9, rem = idx & 511;
            int r = rem >> 2, c = rem & 3;
            const __nv_bfloat16* g = g_PA + ((size_t)(b * 2 + sp) * SS + s0 + r) * KSEL + k0 + c * 8;
            cpasync16(sg + sp * PLANE + r * RPAD + c * 16, g);
        }
#pragma unroll
        for (int i = 0; i < 4; i++) {
            int idx = tid + i * 256;
            int sp = idx >> 9, rem = idx & 511;
            int r = rem >> 2, c = rem & 3;
            const __nv_bfloat16* g = g_Pr + ((size_t)(b * 2 + sp) * DM + d0 + r) * KSEL + k0 + c * 8;
            cpasync16(sg + 2 * PLANE + sp * PLANE + r * RPAD + c * 16, g);
        }
    };

    const u32 aoff = (u32)((wm * 32 + (lid & 15)) * RPAD + (lid >> 4) * 16);
    const u32 boff = (u32)((wn * 64 + (lid & 15)) * RPAD + (lid >> 4) * 16);

    load_stage(0, 0); CP_COMMIT();

#pragma unroll 1
    for (int ks = 0; ks < KSEL / 32; ks++) {
        int buf = ks & 1;
        if (ks < KSEL / 32 - 1) { load_stage(ks + 1, buf ^ 1); CP_COMMIT(); CP_WAIT(1); }
        else                    { CP_WAIT(0); }
        __syncthreads();
        u32 sA = sbase + buf * STGB4;
        u32 sB = sA + 2 * PLANE;
#pragma unroll
        for (int kk = 0; kk < 2; kk++) {
            u32 ah[2][4], am[2][4];
#pragma unroll
            for (int mt = 0; mt < 2; mt++) {
                ldsm4(ah[mt], sA + aoff + mt * (16 * RPAD) + kk * 32);
                ldsm4(am[mt], sA + PLANE + aoff + mt * (16 * RPAD) + kk * 32);
            }
            u32 bh[4][4], bm[4][4];
#pragma unroll
            for (int nt2 = 0; nt2 < 4; nt2++) {
                ldsm4(bh[nt2], sB + boff + nt2 * (16 * RPAD) + kk * 32);
                ldsm4(bm[nt2], sB + PLANE + boff + nt2 * (16 * RPAD) + kk * 32);
            }
#pragma unroll
            for (int mt = 0; mt < 2; mt++)
#pragma unroll
                for (int nt2 = 0; nt2 < 4; nt2++) {
                    mma16816(acc[mt][2 * nt2],     ah[mt], bh[nt2][0], bh[nt2][2]);
                    mma16816(acc[mt][2 * nt2 + 1], ah[mt], bh[nt2][1], bh[nt2][3]);
                    mma16816(acc[mt][2 * nt2],     ah[mt], bm[nt2][0], bm[nt2][2]);
                    mma16816(acc[mt][2 * nt2 + 1], ah[mt], bm[nt2][1], bm[nt2][3]);
                    mma16816(acc[mt][2 * nt2],     am[mt], bh[nt2][0], bh[nt2][2]);
                    mma16816(acc[mt][2 * nt2 + 1], am[mt], bh[nt2][1], bh[nt2][3]);
                }
        }
        __syncthreads();
    }
#pragma unroll
    for (int mt = 0; mt < 2; mt++)
#pragma unroll
        for (int nt = 0; nt < 8; nt++) {
            int row = s0 + wm * 32 + mt * 16 + (lid >> 2);
            int col = d0 + wn * 64 + nt * 8 + 2 * (lid & 3);
            float* po = out + ((size_t)b * SS + row) * DM + col;
            *(float2*)po            = make_float2(acc[mt][nt][0], acc[mt][nt][1]);
            *(float2*)(po + 8 * DM) = make_float2(acc[mt][nt][2], acc[mt][nt][3]);
        }
}

// ---------------- entry (multi-stream fork/join) ----------------
extern "C" void kernel_launch(void* const* d_in, const int* in_sizes, int n_in,
                              void* d_out, int out_size) {
    const float* act  = (const float*)d_in[0];
    const int*   sidx = (const int*)d_in[1];
    int o = (n_in >= 9 && in_sizes[2] == 1) ? 3 : 2;
    const float* cw   = (const float*)d_in[o + 0];
    const float* proj = (const float*)d_in[o + 1];
    const float* w1   = (const float*)d_in[o + 2];
    const float* b1   = (const float*)d_in[o + 3];
    const float* w2   = (const float*)d_in[o + 4];
    const float* b2   = (const float*)d_in[o + 5];
    float* out = (float*)d_out;

    static cudaStream_t s1 = nullptr;
    static cudaEvent_t ev0 = nullptr, ev1 = nullptr, ev2 = nullptr, ev3 = nullptr;
    if (s1 == nullptr) {
        cudaStreamCreateWithFlags(&s1, cudaStreamNonBlocking);
        cudaEventCreateWithFlags(&ev0, cudaEventDisableTiming);
        cudaEventCreateWithFlags(&ev1, cudaEventDisableTiming);
        cudaEventCreateWithFlags(&ev2, cudaEventDisableTiming);
        cudaEventCreateWithFlags(&ev3, cudaEventDisableTiming);
        cudaFuncSetAttribute(k_gemm1a, cudaFuncAttributeMaxDynamicSharedMemorySize, GSMEM1);
        cudaFuncSetAttribute(k_refine, cudaFuncAttributeMaxDynamicSharedMemorySize, GSMEM4);
        cudaFuncSetAttribute(k_gemm3t, cudaFuncAttributeMaxDynamicSharedMemorySize, GSMEM4);
    }

    // fork: A m-plane split + MLP chain on s1
    cudaEventRecord(ev0, 0);
    cudaStreamWaitEvent(s1, ev0, 0);
    k_splitAm<<<(BB * SS * KIN / 4) / 256, 256, 0, s1>>>(act);
    k_initMask<<<(BB * NIN + 255) / 256, 256, 0, s1>>>();
    k_scatter<<<(BB * KIN + 255) / 256, 256, 0, s1>>>(sidx);
    k_hidden<<<HID, 256, 0, s1>>>(w1, b1);
    k_relsig<<<NP / 8, 256, 0, s1>>>(w2, b2);
    cudaEventRecord(ev1, s1);

    // main chain
    k_initScore<<<(BB * NP + 255) / 256, 256>>>();
    k_splitAh<<<(BB * SS * KIN / 4) / 256, 256>>>(act);
    k_gatherBh<<<NP, 256>>>(cw, sidx);
    k_gemm1a<<<dim3(NP / 128, SS / 128, BB), 256, GSMEM1>>>();

    // join
    cudaStreamWaitEvent(0, ev1, 0);
    k_topkc<<<BB, 1024>>>();
    k_gatherBc<<<BB * NC, 256>>>(cw, sidx);
    k_refine<<<dim3(NC / 128, SS / 128, BB), 256, GSMEM4>>>();
    k_rescore<<<BB, NCP>>>();

    // fork: projsplit on s1, compact on main
    cudaEventRecord(ev2, 0);
    cudaStreamWaitEvent(s1, ev2, 0);
    k_projsplit<<<dim3(KSEL / 32, DM / 32, BB), dim3(32, 8), 0, s1>>>(proj);
    cudaEventRecord(ev3, s1);
    k_compact<<<BB * SS / 8, 256>>>();
    cudaStreamWaitEvent(0, ev3, 0);

    k_gemm3t<<<dim3(DM / 128, SS / 128, BB), 256, GSMEM4>>>(out);
}